// round 13
// baseline (speedup 1.0000x reference)
#include <cuda_runtime.h>
#include <cuda_fp16.h>
#include <math.h>
#include <stdint.h>

#define D      256
#define NN     100000
#define EE     1000000
#define HALF_E (EE / 2)
#define RR     474
#define SCAN_BS 1024
#define NB_SCAN ((NN + SCAN_BS - 1) / SCAN_BS)   // 98
#define BN_EPS 1e-5f

#define KTOT   768          // combined K: [pre_in | pre_out | x]
#define NKS    24           // 768 / 32 (k32 per stage)
#define GEMM_MBLK ((NN + 127) / 128)   // 782
#define GE_BLOCKS ((EE + 255) / 256)   // 3907
#define MISC_BLOCKS (KTOT + 1 + RR)    // 1243
#define XCONV_THREADS (NN * 32 + RR * 32)
#define XCONV_BLOCKS ((XCONV_THREADS + 255) / 256)

// SMEM stage: A (128 rows x 64B data + 16B pad) | B (128 x 80B)
#define ROWB    80
#define ASPL    (128 * ROWB)       // 10240
#define STAGE   (2 * ASPL)         // 20480
#define NSTAGE  3
#define SM_STATS (NSTAGE * STAGE)          // 61440
#define SMEM_GEMM (SM_STATS + 1024)        // 62464

// ---------------- static device scratch ----------------
struct ZeroBlk {
    int   cnt[NN];
    float colsum[D];
    float colsumsq[D];
    int   flag;
    int   total;
};
__device__ ZeroBlk g_zb;

__device__ __half g_A[(size_t)NN * KTOT];      // 153.6 MB, fp16
__device__ __half g_B[(size_t)D * KTOT];       // [n][k] fp16
__device__ __half g_xh[(size_t)NN * D];        // 51.2 MB, fp16 copy of x
__device__ __half g_rh[(size_t)RR * D];        // fp16 copy of r
__device__ int      g_start[NN];
__device__ int      g_cursor[NN];
__device__ unsigned g_epack[EE];   // mode<<31 | et<<17 | col
__device__ float    g_dinv[NN];
__device__ float    g_bias2[D];
__device__ float    g_scale[D];
__device__ float    g_shift[D];

// ---------------- helpers ----------------
__device__ __forceinline__ uint32_t smem_u32(const void* p) {
    uint32_t a;
    asm("{ .reg .u64 t; cvta.to.shared.u64 t, %1; cvt.u32.u64 %0, t; }" : "=r"(a) : "l"(p));
    return a;
}

#define CP_ASYNC16(dst, src, sz) \
    asm volatile("cp.async.cg.shared.global [%0], [%1], 16, %2;" \
        :: "r"(dst), "l"(src), "r"(sz) : "memory")
#define CP_COMMIT() asm volatile("cp.async.commit_group;" ::: "memory")
#define CP_WAIT2()  asm volatile("cp.async.wait_group 2;" ::: "memory")

#define LDMATRIX_X4(r0, r1, r2, r3, addr) \
    asm volatile("ldmatrix.sync.aligned.m8n8.x4.shared.b16 {%0,%1,%2,%3}, [%4];" \
        : "=r"(r0), "=r"(r1), "=r"(r2), "=r"(r3) : "r"(addr))

#define MMA16816F16(C, A, B0, B1) \
    asm volatile("mma.sync.aligned.m16n8k16.row.col.f32.f16.f16.f32 " \
        "{%0,%1,%2,%3}, {%4,%5,%6,%7}, {%8,%9}, {%0,%1,%2,%3};" \
        : "+f"((C)[0]), "+f"((C)[1]), "+f"((C)[2]), "+f"((C)[3]) \
        : "r"((A)[0]), "r"((A)[1]), "r"((A)[2]), "r"((A)[3]), "r"(B0), "r"(B1))

// convert 8 fp32 -> fp16 packed in uint4
__device__ __forceinline__ uint4 pack_half8(const float* v) {
    uint32_t h[4];
#pragma unroll
    for (int q = 0; q < 4; q++) {
        __half2 p = __floats2half2_rn(v[2 * q], v[2 * q + 1]);
        h[q] = *reinterpret_cast<uint32_t*>(&p);
    }
    return make_uint4(h[0], h[1], h[2], h[3]);
}

// ---------------- launch 1: edge count histogram + misc (fused) ----------------
__global__ void k_countmisc(const int* __restrict__ rowp,
                            const float* __restrict__ w_in,
                            const float* __restrict__ w_out,
                            const float* __restrict__ w_loop,
                            const float* __restrict__ bias,
                            const float* __restrict__ loop_rel,
                            const float* __restrict__ r,
                            const float* __restrict__ w_rel,
                            float* __restrict__ rout) {
    int b = blockIdx.x;
    if (b < GE_BLOCKS) {
        int e = b * 256 + threadIdx.x;
        if (e < EE) atomicAdd(&g_zb.cnt[rowp[e]], 1);
        return;
    }
    int mb = b - GE_BLOCKS;
    int n = threadIdx.x;
    if (n >= D) return;
    if (mb < KTOT) {                      // W transpose to fp16
        int k = mb;
        const float* W = (k < 256) ? w_in : (k < 512) ? w_out : w_loop;
        float v = W[(size_t)(k & 255) * D + n];
        g_B[(size_t)n * KTOT + k] = __float2half_rn(v);
    } else if (mb == KTOT) {              // bias2 = bias - loop_rel @ w_loop
        float acc = bias[n];
        for (int k = 0; k < D; k++)
            acc -= loop_rel[k] * w_loop[k * D + n];
        g_bias2[n] = acc;
    } else {                              // relgemm row
        int row = mb - KTOT - 1;
        const float* rr = r + (size_t)row * D;
        float acc = 0.f;
#pragma unroll 8
        for (int k = 0; k < D; k++)
            acc += rr[k] * w_rel[k * D + n];
        rout[(size_t)row * D + n] = acc;
    }
}

// ---------------- launch 2: x, r -> fp16 (x_h also seeds g_A cols [512,768)) ----------------
__global__ void k_xconv(const float* __restrict__ x, const float* __restrict__ r) {
    int gid = blockIdx.x * 256 + threadIdx.x;
    if (gid < NN * 32) {
        int row = gid >> 5, c8 = gid & 31;
        const float4* src = (const float4*)(x + (size_t)row * D + c8 * 8);
        float4 v0 = src[0], v1 = src[1];
        float v[8] = {v0.x, v0.y, v0.z, v0.w, v1.x, v1.y, v1.z, v1.w};
        uint4 hv = pack_half8(v);
        *(uint4*)(g_xh + (size_t)row * D + c8 * 8) = hv;
        *(uint4*)(g_A + (size_t)row * KTOT + 512 + c8 * 8) = hv;
    } else {
        int g2 = gid - NN * 32;
        if (g2 < RR * 32) {
            int row = g2 >> 5, c8 = g2 & 31;
            const float4* src = (const float4*)(r + (size_t)row * D + c8 * 8);
            float4 v0 = src[0], v1 = src[1];
            float v[8] = {v0.x, v0.y, v0.z, v0.w, v1.x, v1.y, v1.z, v1.w};
            *(uint4*)(g_rh + (size_t)row * D + c8 * 8) = pack_half8(v);
        }
    }
}

// ---------------- launch 3: scan + dinv + start/cursor + edge fill (fused) ----------------
__global__ void k_scanfill(const int* __restrict__ rowp,
                           const int* __restrict__ colp,
                           const int* __restrict__ etp) {
    __shared__ int s[SCAN_BS];
    __shared__ int base_sh;
    int t = threadIdx.x;
    int bid = blockIdx.x;
    int i = bid * SCAN_BS + t;
    int v = (i < NN) ? g_zb.cnt[i] : 0;
    if (i < NN) g_dinv[i] = (v > 0) ? rsqrtf((float)v) : 0.f;
    s[t] = v;
    __syncthreads();
    for (int off = 1; off < SCAN_BS; off <<= 1) {
        int a = (t >= off) ? s[t - off] : 0;
        __syncthreads();
        s[t] += a;
        __syncthreads();
    }
    int incl = s[t];
    if (t == 0) {
        int btot = s[SCAN_BS - 1];
        while (atomicAdd(&g_zb.flag, 0) != bid) {}
        __threadfence();
        int b = g_zb.total;
        g_zb.total = b + btot;
        __threadfence();
        atomicExch(&g_zb.flag, bid + 1);
        base_sh = b;
    }
    __syncthreads();
    if (i < NN) {
        int st = base_sh + incl - v;
        g_start[i] = st;
        g_cursor[i] = st;
    }
    if (t == 0) {
        while (atomicAdd(&g_zb.flag, 0) != NB_SCAN) {}
        base_sh = 0;
    }
    __syncthreads();
    __threadfence();
    int nthreads = NB_SCAN * SCAN_BS;
    for (int e = bid * SCAN_BS + t; e < EE; e += nthreads) {
        int pos = atomicAdd(&g_cursor[rowp[e]], 1);
        unsigned pk = ((e < HALF_E) ? 0u : 0x80000000u) |
                      ((unsigned)etp[e] << 17) | (unsigned)colp[e];
        g_epack[pos] = pk;
    }
}

// ---------------- launch 4 (profiled): aggregate, half2 math ----------------
__global__ void k_aggregate() {
    int node = blockIdx.x * 8 + (threadIdx.x >> 5);
    if (node >= NN) return;
    int lane = threadIdx.x & 31;
    int base = lane * 8;
    size_t rb = (size_t)node * KTOT;

    __half2 zero = __float2half2_rn(0.f);
    __half2 ain[4] = {zero, zero, zero, zero};
    __half2 aout[4] = {zero, zero, zero, zero};

    int s = g_start[node];
    int c = g_zb.cnt[node];
    float di = g_dinv[node];
    int end = s + c;
    int p = s;

    for (; p + 2 <= end; p += 2) {
        unsigned pk0 = g_epack[p], pk1 = g_epack[p + 1];
        int cl0 = pk0 & 0x1FFFF, et0 = (pk0 >> 17) & 0x1FF;
        int cl1 = pk1 & 0x1FFFF, et1 = (pk1 >> 17) & 0x1FF;
        __half2 n0 = __float2half2_rn(di * g_dinv[cl0]);
        __half2 n1 = __float2half2_rn(di * g_dinv[cl1]);
        uint4 xa = *(const uint4*)(g_xh + (size_t)cl0 * D + base);
        uint4 ra = *(const uint4*)(g_rh + (size_t)et0 * D + base);
        uint4 xb = *(const uint4*)(g_xh + (size_t)cl1 * D + base);
        uint4 rv = *(const uint4*)(g_rh + (size_t)et1 * D + base);
        const __half2* xah = (const __half2*)&xa;
        const __half2* rah = (const __half2*)&ra;
        const __half2* xbh = (const __half2*)&xb;
        const __half2* rbh = (const __half2*)&rv;
        __half2* a0 = (pk0 & 0x80000000u) ? aout : ain;
        __half2* a1 = (pk1 & 0x80000000u) ? aout : ain;
#pragma unroll
        for (int q = 0; q < 4; q++) {
            a0[q] = __hfma2(__hsub2(xah[q], rah[q]), n0, a0[q]);
            a1[q] = __hfma2(__hsub2(xbh[q], rbh[q]), n1, a1[q]);
        }
    }
    if (p < end) {
        unsigned pk = g_epack[p];
        int cl = pk & 0x1FFFF, et = (pk >> 17) & 0x1FF;
        __half2 nrm = __float2half2_rn(di * g_dinv[cl]);
        uint4 xa = *(const uint4*)(g_xh + (size_t)cl * D + base);
        uint4 ra = *(const uint4*)(g_rh + (size_t)et * D + base);
        const __half2* xah = (const __half2*)&xa;
        const __half2* rah = (const __half2*)&ra;
        __half2* a0 = (pk & 0x80000000u) ? aout : ain;
#pragma unroll
        for (int q = 0; q < 4; q++)
            a0[q] = __hfma2(__hsub2(xah[q], rah[q]), nrm, a0[q]);
    }
    *(uint4*)(g_A + rb + base)       = *(uint4*)ain;
    *(uint4*)(g_A + rb + 256 + base) = *(uint4*)aout;
}

// ---------------- launch 5: mma.sync fp16 GEMM (M128 x N128, k32 stages) ----------------
__device__ __forceinline__ void load_stage(uint32_t sb, int buf, int kOff,
                                           int rowBase, int colBase, int tid) {
    uint32_t base = sb + buf * STAGE;
#pragma unroll
    for (int i = 0; i < 4; i++) {
        int c = tid + i * 256;
        int isB = c >> 9;
        int rem = c & 511;
        int row = rem >> 2, q = rem & 3;
        uint32_t dst = base + isB * ASPL + row * ROWB + q * 16;
        const __half* src;
        int sz = 16;
        if (!isB) {
            int gr = rowBase + row;
            if (gr >= NN) { gr = 0; sz = 0; }
            src = g_A + (size_t)gr * KTOT + kOff + q * 8;
        } else {
            int gc = colBase + row;
            src = g_B + (size_t)gc * KTOT + kOff + q * 8;
        }
        CP_ASYNC16(dst, (const void*)src, sz);
    }
}

__global__ void __launch_bounds__(256, 2)
k_gemm_mma(float* __restrict__ hout) {
    extern __shared__ char smem[];
    uint32_t sb = smem_u32(smem);
    int tid = threadIdx.x;
    int lane = tid & 31, wid = tid >> 5;
    int warp_m = wid & 1;
    int warp_n = wid >> 1;
    int colBase = blockIdx.x * 128;
    int rowBase = blockIdx.y * 128;

    float c[4][4][4];
#pragma unroll
    for (int i = 0; i < 4; i++)
#pragma unroll
        for (int j = 0; j < 4; j++)
#pragma unroll
            for (int q = 0; q < 4; q++) c[i][j][q] = 0.f;

#pragma unroll
    for (int s = 0; s < NSTAGE; s++) {
        load_stage(sb, s, s * 32, rowBase, colBase, tid);
        CP_COMMIT();
    }

    uint32_t a_off = (lane & 15) * ROWB + (lane >> 4) * 16;
    uint32_t b_off = (((lane >> 4) << 3) + (lane & 7)) * ROWB + ((lane >> 3) & 1) * 16;

    for (int it = 0; it < NKS; it++) {
        CP_WAIT2();
        __syncthreads();
        uint32_t st = sb + (it % 3) * STAGE;

#pragma unroll
        for (int ks2 = 0; ks2 < 2; ks2++) {
            uint32_t kb = ks2 * 32;
            uint32_t a[4][4];
#pragma unroll
            for (int mt = 0; mt < 4; mt++) {
                uint32_t addr = st + (warp_m * 64 + mt * 16) * ROWB + kb + a_off;
                LDMATRIX_X4(a[mt][0], a[mt][1], a[mt][2], a[mt][3], addr);
            }
            uint32_t b[2][4];
#pragma unroll
            for (int pr = 0; pr < 2; pr++) {
                uint32_t addr = st + ASPL + (warp_n * 32 + pr * 16) * ROWB + kb + b_off;
                LDMATRIX_X4(b[pr][0], b[pr][1], b[pr][2], b[pr][3], addr);
            }
#pragma unroll
            for (int mt = 0; mt < 4; mt++)
#pragma unroll
                for (int nt = 0; nt < 4; nt++) {
                    int pr = nt >> 1, ix = (nt & 1) * 2;
                    MMA16816F16(c[mt][nt], a[mt], b[pr][ix], b[pr][ix + 1]);
                }
        }
        __syncthreads();
        if (it + 3 < NKS)
            load_stage(sb, it % 3, (it + 3) * 32, rowBase, colBase, tid);
        CP_COMMIT();
    }

    // ---- epilogue: write hout (fp32) + per-CTA column stats ----
    float* cs  = (float*)(smem + SM_STATS);
    float* css = (float*)(smem + SM_STATS) + 128;
    __syncthreads();
    ((float*)(smem + SM_STATS))[tid] = 0.f;
    __syncthreads();

#pragma unroll
    for (int nt = 0; nt < 4; nt++) {
        int lcol = warp_n * 32 + nt * 8 + (lane & 3) * 2;
        int col = colBase + lcol;
        float b0 = g_bias2[col], b1 = g_bias2[col + 1];
        float s0 = 0.f, s1 = 0.f, q0 = 0.f, q1 = 0.f;
#pragma unroll
        for (int mt = 0; mt < 4; mt++) {
            int row = rowBase + warp_m * 64 + mt * 16 + (lane >> 2);
            if (row < NN) {
                float v0 = c[mt][nt][0] + b0, v1 = c[mt][nt][1] + b1;
                *(float2*)(hout + (size_t)row * D + col) = make_float2(v0, v1);
                s0 += v0; s1 += v1; q0 += v0 * v0; q1 += v1 * v1;
            }
            int row2 = row + 8;
            if (row2 < NN) {
                float v0 = c[mt][nt][2] + b0, v1 = c[mt][nt][3] + b1;
                *(float2*)(hout + (size_t)row2 * D + col) = make_float2(v0, v1);
                s0 += v0; s1 += v1; q0 += v0 * v0; q1 += v1 * v1;
            }
        }
        atomicAdd(&cs[lcol], s0);
        atomicAdd(&cs[lcol + 1], s1);
        atomicAdd(&css[lcol], q0);
        atomicAdd(&css[lcol + 1], q1);
    }
    __syncthreads();
    if (tid < 128) atomicAdd(&g_zb.colsum[colBase + tid], cs[tid]);
    else           atomicAdd(&g_zb.colsumsq[colBase + (tid - 128)], css[tid - 128]);
}

// ---------------- BN finalize / apply ----------------
__global__ void k_bn_finalize(const float* __restrict__ gamma,
                              const float* __restrict__ beta) {
    int c = threadIdx.x;
    float mean = g_zb.colsum[c] / (float)NN;
    float var = g_zb.colsumsq[c] / (float)NN - mean * mean;
    float inv = rsqrtf(var + BN_EPS);
    float sc = gamma[c] * inv;
    g_scale[c] = sc;
    g_shift[c] = beta[c] - mean * sc;
}
__global__ void k_bn_apply(float* __restrict__ hout) {
    size_t i4 = (size_t)blockIdx.x * blockDim.x + threadIdx.x;
    size_t total4 = (size_t)NN * D / 4;
    if (i4 < total4) {
        int c = (int)((i4 & 63) * 4);
        float4 v = *(float4*)(hout + i4 * 4);
        v.x = tanhf(v.x * g_scale[c + 0] + g_shift[c + 0]);
        v.y = tanhf(v.y * g_scale[c + 1] + g_shift[c + 1]);
        v.z = tanhf(v.z * g_scale[c + 2] + g_shift[c + 2]);
        v.w = tanhf(v.w * g_scale[c + 3] + g_shift[c + 3]);
        *(float4*)(hout + i4 * 4) = v;
    }
}

// ---------------- launch ----------------
extern "C" void kernel_launch(void* const* d_in, const int* in_sizes, int n_in,
                              void* d_out, int out_size) {
    const float* x        = (const float*)d_in[0];
    const float* r        = (const float*)d_in[1];
    const float* w_in     = (const float*)d_in[2];
    const float* w_out    = (const float*)d_in[3];
    const float* w_loop   = (const float*)d_in[4];
    const float* w_rel    = (const float*)d_in[5];
    const float* loop_rel = (const float*)d_in[6];
    const float* bias     = (const float*)d_in[7];
    const float* bn_gamma = (const float*)d_in[8];
    const float* bn_beta  = (const float*)d_in[9];
    const int*   edge_idx = (const int*)d_in[10];
    const int*   edge_typ = (const int*)d_in[11];

    const int* rowp = edge_idx;
    const int* colp = edge_idx + EE;

    float* hout = (float*)d_out;
    float* rout = (float*)d_out + (size_t)NN * D;

    cudaFuncSetAttribute(k_gemm_mma, cudaFuncAttributeMaxDynamicSharedMemorySize, SMEM_GEMM);

    void* zb_addr = nullptr;
    cudaGetSymbolAddress(&zb_addr, g_zb);
    cudaMemsetAsync(zb_addr, 0, sizeof(ZeroBlk));

    k_countmisc<<<GE_BLOCKS + MISC_BLOCKS, 256>>>(rowp, w_in, w_out, w_loop,
                                                  bias, loop_rel, r, w_rel, rout); // 1
    k_xconv<<<XCONV_BLOCKS, 256>>>(x, r);                                          // 2
    k_scanfill<<<NB_SCAN, SCAN_BS>>>(rowp, colp, edge_typ);                        // 3
    k_aggregate<<<(NN + 7) / 8, 256>>>();                                          // 4 (profiled)
    dim3 gg(2, GEMM_MBLK);
    k_gemm_mma<<<gg, 256, SMEM_GEMM>>>(hout);                                      // 5
    k_bn_finalize<<<1, D>>>(bn_gamma, bn_beta);                                    // 6
    k_bn_apply<<<(int)(((size_t)NN * D / 4 + 255) / 256), 256>>>(hout);            // 7
}

// round 14
// speedup vs baseline: 1.0667x; 1.0667x over previous
#include <cuda_runtime.h>
#include <cuda_fp16.h>
#include <math.h>
#include <stdint.h>

#define D      256
#define NN     100000
#define EE     1000000
#define HALF_E (EE / 2)
#define RR     474
#define SCAN_BS 1024
#define NB_SCAN ((NN + SCAN_BS - 1) / SCAN_BS)   // 98
#define BN_EPS 1e-5f

#define KTOT   768          // combined K: [pre_in | pre_out | x]
#define NKS    24           // 768 / 32 (k32 per stage)
#define GEMM_MBLK ((NN + 127) / 128)   // 782
#define GE_BLOCKS ((EE + 255) / 256)   // 3907
#define MISC_BLOCKS (KTOT + 1 + RR)    // 1243
#define XCONV_THREADS (NN * 32 + RR * 32)
#define XCONV_BLOCKS ((XCONV_THREADS + 255) / 256)

// SMEM stage: A (128 rows x 64B data + 16B pad) | B (128 x 80B)
#define ROWB    80
#define ASPL    (128 * ROWB)       // 10240
#define STAGE   (2 * ASPL)         // 20480
#define NSTAGE  3
#define SM_STATS (NSTAGE * STAGE)          // 61440
#define SMEM_GEMM (SM_STATS + 1024)        // 62464

// ---------------- static device scratch ----------------
struct ZeroBlk {
    int   cnt[NN];
    float colsum[D];
    float colsumsq[D];
    int   flag;
    int   total;
};
__device__ ZeroBlk g_zb;

__device__ __half g_A[(size_t)NN * KTOT];      // 153.6 MB, fp16
__device__ __half g_B[(size_t)D * KTOT];       // [n][k] fp16
__device__ __half g_xh[(size_t)NN * D];        // 51.2 MB, fp16 copy of x
__device__ __half g_rh[(size_t)RR * D];        // fp16 copy of r
__device__ int      g_start[NN];
__device__ int      g_cursor[NN];
__device__ unsigned g_epack[EE];   // mode<<31 | et<<17 | col
__device__ float    g_dinv[NN];
__device__ float    g_bias2[D];
__device__ float    g_scale[D];
__device__ float    g_shift[D];

// ---------------- helpers ----------------
__device__ __forceinline__ uint32_t smem_u32(const void* p) {
    uint32_t a;
    asm("{ .reg .u64 t; cvta.to.shared.u64 t, %1; cvt.u32.u64 %0, t; }" : "=r"(a) : "l"(p));
    return a;
}

#define CP_ASYNC16(dst, src, sz) \
    asm volatile("cp.async.cg.shared.global [%0], [%1], 16, %2;" \
        :: "r"(dst), "l"(src), "r"(sz) : "memory")
#define CP_COMMIT() asm volatile("cp.async.commit_group;" ::: "memory")
#define CP_WAIT2()  asm volatile("cp.async.wait_group 2;" ::: "memory")

#define LDMATRIX_X4(r0, r1, r2, r3, addr) \
    asm volatile("ldmatrix.sync.aligned.m8n8.x4.shared.b16 {%0,%1,%2,%3}, [%4];" \
        : "=r"(r0), "=r"(r1), "=r"(r2), "=r"(r3) : "r"(addr))

#define MMA16816F16(C, A, B0, B1) \
    asm volatile("mma.sync.aligned.m16n8k16.row.col.f32.f16.f16.f32 " \
        "{%0,%1,%2,%3}, {%4,%5,%6,%7}, {%8,%9}, {%0,%1,%2,%3};" \
        : "+f"((C)[0]), "+f"((C)[1]), "+f"((C)[2]), "+f"((C)[3]) \
        : "r"((A)[0]), "r"((A)[1]), "r"((A)[2]), "r"((A)[3]), "r"(B0), "r"(B1))

// convert 8 fp32 -> fp16 packed in uint4
__device__ __forceinline__ uint4 pack_half8(const float* v) {
    uint32_t h[4];
#pragma unroll
    for (int q = 0; q < 4; q++) {
        __half2 p = __floats2half2_rn(v[2 * q], v[2 * q + 1]);
        h[q] = *reinterpret_cast<uint32_t*>(&p);
    }
    return make_uint4(h[0], h[1], h[2], h[3]);
}

// ---------------- launch 1: edge count histogram + misc (fused) ----------------
__global__ void k_countmisc(const int* __restrict__ rowp,
                            const float* __restrict__ w_in,
                            const float* __restrict__ w_out,
                            const float* __restrict__ w_loop,
                            const float* __restrict__ bias,
                            const float* __restrict__ loop_rel,
                            const float* __restrict__ r,
                            const float* __restrict__ w_rel,
                            float* __restrict__ rout) {
    int b = blockIdx.x;
    if (b < GE_BLOCKS) {
        int e = b * 256 + threadIdx.x;
        if (e < EE) atomicAdd(&g_zb.cnt[rowp[e]], 1);
        return;
    }
    int mb = b - GE_BLOCKS;
    int n = threadIdx.x;
    if (n >= D) return;
    if (mb < KTOT) {                      // W transpose to fp16
        int k = mb;
        const float* W = (k < 256) ? w_in : (k < 512) ? w_out : w_loop;
        float v = W[(size_t)(k & 255) * D + n];
        g_B[(size_t)n * KTOT + k] = __float2half_rn(v);
    } else if (mb == KTOT) {              // bias2 = bias - loop_rel @ w_loop
        float acc = bias[n];
        for (int k = 0; k < D; k++)
            acc -= loop_rel[k] * w_loop[k * D + n];
        g_bias2[n] = acc;
    } else {                              // relgemm row
        int row = mb - KTOT - 1;
        const float* rr = r + (size_t)row * D;
        float acc = 0.f;
#pragma unroll 8
        for (int k = 0; k < D; k++)
            acc += rr[k] * w_rel[k * D + n];
        rout[(size_t)row * D + n] = acc;
    }
}

// ---------------- launch 2: x, r -> fp16 (x_h also seeds g_A cols [512,768)) ----------------
__global__ void k_xconv(const float* __restrict__ x, const float* __restrict__ r) {
    int gid = blockIdx.x * 256 + threadIdx.x;
    if (gid < NN * 32) {
        int row = gid >> 5, c8 = gid & 31;
        const float4* src = (const float4*)(x + (size_t)row * D + c8 * 8);
        float4 v0 = src[0], v1 = src[1];
        float v[8] = {v0.x, v0.y, v0.z, v0.w, v1.x, v1.y, v1.z, v1.w};
        uint4 hv = pack_half8(v);
        *(uint4*)(g_xh + (size_t)row * D + c8 * 8) = hv;
        *(uint4*)(g_A + (size_t)row * KTOT + 512 + c8 * 8) = hv;
    } else {
        int g2 = gid - NN * 32;
        if (g2 < RR * 32) {
            int row = g2 >> 5, c8 = g2 & 31;
            const float4* src = (const float4*)(r + (size_t)row * D + c8 * 8);
            float4 v0 = src[0], v1 = src[1];
            float v[8] = {v0.x, v0.y, v0.z, v0.w, v1.x, v1.y, v1.z, v1.w};
            *(uint4*)(g_rh + (size_t)row * D + c8 * 8) = pack_half8(v);
        }
    }
}

// ---------------- launch 3: scan + dinv + start/cursor + edge fill (fused) ----------------
__global__ void k_scanfill(const int* __restrict__ rowp,
                           const int* __restrict__ colp,
                           const int* __restrict__ etp) {
    __shared__ int s[SCAN_BS];
    __shared__ int base_sh;
    int t = threadIdx.x;
    int bid = blockIdx.x;
    int i = bid * SCAN_BS + t;
    int v = (i < NN) ? g_zb.cnt[i] : 0;
    if (i < NN) g_dinv[i] = (v > 0) ? rsqrtf((float)v) : 0.f;
    s[t] = v;
    __syncthreads();
    for (int off = 1; off < SCAN_BS; off <<= 1) {
        int a = (t >= off) ? s[t - off] : 0;
        __syncthreads();
        s[t] += a;
        __syncthreads();
    }
    int incl = s[t];
    if (t == 0) {
        int btot = s[SCAN_BS - 1];
        while (atomicAdd(&g_zb.flag, 0) != bid) {}
        __threadfence();
        int b = g_zb.total;
        g_zb.total = b + btot;
        __threadfence();
        atomicExch(&g_zb.flag, bid + 1);
        base_sh = b;
    }
    __syncthreads();
    if (i < NN) {
        int st = base_sh + incl - v;
        g_start[i] = st;
        g_cursor[i] = st;
    }
    if (t == 0) {
        while (atomicAdd(&g_zb.flag, 0) != NB_SCAN) {}
        base_sh = 0;
    }
    __syncthreads();
    __threadfence();
    int nthreads = NB_SCAN * SCAN_BS;
    for (int e = bid * SCAN_BS + t; e < EE; e += nthreads) {
        int pos = atomicAdd(&g_cursor[rowp[e]], 1);
        unsigned pk = ((e < HALF_E) ? 0u : 0x80000000u) |
                      ((unsigned)etp[e] << 17) | (unsigned)colp[e];
        g_epack[pos] = pk;
    }
}

// ---------------- launch 4 (profiled): aggregate, HSUB2 + fp32 accumulate ----------------
__global__ void k_aggregate() {
    int node = blockIdx.x * 8 + (threadIdx.x >> 5);
    if (node >= NN) return;
    int lane = threadIdx.x & 31;
    int base = lane * 8;
    size_t rb = (size_t)node * KTOT;

    float ain[8] = {0}, aout[8] = {0};
    int s = g_start[node];
    int c = g_zb.cnt[node];
    float di = g_dinv[node];
    int end = s + c;
    int p = s;

    for (; p + 2 <= end; p += 2) {
        unsigned pk0 = g_epack[p], pk1 = g_epack[p + 1];
        int cl0 = pk0 & 0x1FFFF, et0 = (pk0 >> 17) & 0x1FF;
        int cl1 = pk1 & 0x1FFFF, et1 = (pk1 >> 17) & 0x1FF;
        float n0 = di * g_dinv[cl0];
        float n1 = di * g_dinv[cl1];
        uint4 xa = *(const uint4*)(g_xh + (size_t)cl0 * D + base);
        uint4 ra = *(const uint4*)(g_rh + (size_t)et0 * D + base);
        uint4 xb = *(const uint4*)(g_xh + (size_t)cl1 * D + base);
        uint4 rv = *(const uint4*)(g_rh + (size_t)et1 * D + base);
        const __half2* xah = (const __half2*)&xa;
        const __half2* rah = (const __half2*)&ra;
        const __half2* xbh = (const __half2*)&xb;
        const __half2* rbh = (const __half2*)&rv;
        float* a0 = (pk0 & 0x80000000u) ? aout : ain;
        float* a1 = (pk1 & 0x80000000u) ? aout : ain;
#pragma unroll
        for (int q = 0; q < 4; q++) {
            float2 f0 = __half22float2(__hsub2(xah[q], rah[q]));
            a0[2 * q]     += n0 * f0.x;
            a0[2 * q + 1] += n0 * f0.y;
            float2 f1 = __half22float2(__hsub2(xbh[q], rbh[q]));
            a1[2 * q]     += n1 * f1.x;
            a1[2 * q + 1] += n1 * f1.y;
        }
    }
    if (p < end) {
        unsigned pk = g_epack[p];
        int cl = pk & 0x1FFFF, et = (pk >> 17) & 0x1FF;
        float nrm = di * g_dinv[cl];
        uint4 xa = *(const uint4*)(g_xh + (size_t)cl * D + base);
        uint4 ra = *(const uint4*)(g_rh + (size_t)et * D + base);
        const __half2* xah = (const __half2*)&xa;
        const __half2* rah = (const __half2*)&ra;
        float* a0 = (pk & 0x80000000u) ? aout : ain;
#pragma unroll
        for (int q = 0; q < 4; q++) {
            float2 f0 = __half22float2(__hsub2(xah[q], rah[q]));
            a0[2 * q]     += nrm * f0.x;
            a0[2 * q + 1] += nrm * f0.y;
        }
    }
    *(uint4*)(g_A + rb + base)       = pack_half8(ain);
    *(uint4*)(g_A + rb + 256 + base) = pack_half8(aout);
}

// ---------------- launch 5: mma.sync fp16 GEMM (M128 x N128, k32 stages) ----------------
__device__ __forceinline__ void load_stage(uint32_t sb, int buf, int kOff,
                                           int rowBase, int colBase, int tid) {
    uint32_t base = sb + buf * STAGE;
#pragma unroll
    for (int i = 0; i < 4; i++) {
        int c = tid + i * 256;
        int isB = c >> 9;
        int rem = c & 511;
        int row = rem >> 2, q = rem & 3;
        uint32_t dst = base + isB * ASPL + row * ROWB + q * 16;
        const __half* src;
        int sz = 16;
        if (!isB) {
            int gr = rowBase + row;
            if (gr >= NN) { gr = 0; sz = 0; }
            src = g_A + (size_t)gr * KTOT + kOff + q * 8;
        } else {
            int gc = colBase + row;
            src = g_B + (size_t)gc * KTOT + kOff + q * 8;
        }
        CP_ASYNC16(dst, (const void*)src, sz);
    }
}

__global__ void __launch_bounds__(256, 2)
k_gemm_mma(float* __restrict__ hout) {
    extern __shared__ char smem[];
    uint32_t sb = smem_u32(smem);
    int tid = threadIdx.x;
    int lane = tid & 31, wid = tid >> 5;
    int warp_m = wid & 1;
    int warp_n = wid >> 1;
    int colBase = blockIdx.x * 128;
    int rowBase = blockIdx.y * 128;

    float c[4][4][4];
#pragma unroll
    for (int i = 0; i < 4; i++)
#pragma unroll
        for (int j = 0; j < 4; j++)
#pragma unroll
            for (int q = 0; q < 4; q++) c[i][j][q] = 0.f;

#pragma unroll
    for (int s = 0; s < NSTAGE; s++) {
        load_stage(sb, s, s * 32, rowBase, colBase, tid);
        CP_COMMIT();
    }

    uint32_t a_off = (lane & 15) * ROWB + (lane >> 4) * 16;
    uint32_t b_off = (((lane >> 4) << 3) + (lane & 7)) * ROWB + ((lane >> 3) & 1) * 16;

    for (int it = 0; it < NKS; it++) {
        CP_WAIT2();
        __syncthreads();
        uint32_t st = sb + (it % 3) * STAGE;

#pragma unroll
        for (int ks2 = 0; ks2 < 2; ks2++) {
            uint32_t kb = ks2 * 32;
            uint32_t a[4][4];
#pragma unroll
            for (int mt = 0; mt < 4; mt++) {
                uint32_t addr = st + (warp_m * 64 + mt * 16) * ROWB + kb + a_off;
                LDMATRIX_X4(a[mt][0], a[mt][1], a[mt][2], a[mt][3], addr);
            }
            uint32_t b[2][4];
#pragma unroll
            for (int pr = 0; pr < 2; pr++) {
                uint32_t addr = st + ASPL + (warp_n * 32 + pr * 16) * ROWB + kb + b_off;
                LDMATRIX_X4(b[pr][0], b[pr][1], b[pr][2], b[pr][3], addr);
            }
#pragma unroll
            for (int mt = 0; mt < 4; mt++)
#pragma unroll
                for (int nt = 0; nt < 4; nt++) {
                    int pr = nt >> 1, ix = (nt & 1) * 2;
                    MMA16816F16(c[mt][nt], a[mt], b[pr][ix], b[pr][ix + 1]);
                }
        }
        __syncthreads();
        if (it + 3 < NKS)
            load_stage(sb, it % 3, (it + 3) * 32, rowBase, colBase, tid);
        CP_COMMIT();
    }

    // ---- epilogue: write hout (fp32) + per-CTA column stats ----
    float* cs  = (float*)(smem + SM_STATS);
    float* css = (float*)(smem + SM_STATS) + 128;
    __syncthreads();
    ((float*)(smem + SM_STATS))[tid] = 0.f;
    __syncthreads();

#pragma unroll
    for (int nt = 0; nt < 4; nt++) {
        int lcol = warp_n * 32 + nt * 8 + (lane & 3) * 2;
        int col = colBase + lcol;
        float b0 = g_bias2[col], b1 = g_bias2[col + 1];
        float s0 = 0.f, s1 = 0.f, q0 = 0.f, q1 = 0.f;
#pragma unroll
        for (int mt = 0; mt < 4; mt++) {
            int row = rowBase + warp_m * 64 + mt * 16 + (lane >> 2);
            if (row < NN) {
                float v0 = c[mt][nt][0] + b0, v1 = c[mt][nt][1] + b1;
                *(float2*)(hout + (size_t)row * D + col) = make_float2(v0, v1);
                s0 += v0; s1 += v1; q0 += v0 * v0; q1 += v1 * v1;
            }
            int row2 = row + 8;
            if (row2 < NN) {
                float v0 = c[mt][nt][2] + b0, v1 = c[mt][nt][3] + b1;
                *(float2*)(hout + (size_t)row2 * D + col) = make_float2(v0, v1);
                s0 += v0; s1 += v1; q0 += v0 * v0; q1 += v1 * v1;
            }
        }
        atomicAdd(&cs[lcol], s0);
        atomicAdd(&cs[lcol + 1], s1);
        atomicAdd(&css[lcol], q0);
        atomicAdd(&css[lcol + 1], q1);
    }
    __syncthreads();
    if (tid < 128) atomicAdd(&g_zb.colsum[colBase + tid], cs[tid]);
    else           atomicAdd(&g_zb.colsumsq[colBase + (tid - 128)], css[tid - 128]);
}

// ---------------- BN finalize / apply ----------------
__global__ void k_bn_finalize(const float* __restrict__ gamma,
                              const float* __restrict__ beta) {
    int c = threadIdx.x;
    float mean = g_zb.colsum[c] / (float)NN;
    float var = g_zb.colsumsq[c] / (float)NN - mean * mean;
    float inv = rsqrtf(var + BN_EPS);
    float sc = gamma[c] * inv;
    g_scale[c] = sc;
    g_shift[c] = beta[c] - mean * sc;
}
__global__ void k_bn_apply(float* __restrict__ hout) {
    size_t i4 = (size_t)blockIdx.x * blockDim.x + threadIdx.x;
    size_t total4 = (size_t)NN * D / 4;
    if (i4 < total4) {
        int c = (int)((i4 & 63) * 4);
        float4 v = *(float4*)(hout + i4 * 4);
        v.x = tanhf(v.x * g_scale[c + 0] + g_shift[c + 0]);
        v.y = tanhf(v.y * g_scale[c + 1] + g_shift[c + 1]);
        v.z = tanhf(v.z * g_scale[c + 2] + g_shift[c + 2]);
        v.w = tanhf(v.w * g_scale[c + 3] + g_shift[c + 3]);
        *(float4*)(hout + i4 * 4) = v;
    }
}

// ---------------- launch ----------------
extern "C" void kernel_launch(void* const* d_in, const int* in_sizes, int n_in,
                              void* d_out, int out_size) {
    const float* x        = (const float*)d_in[0];
    const float* r        = (const float*)d_in[1];
    const float* w_in     = (const float*)d_in[2];
    const float* w_out    = (const float*)d_in[3];
    const float* w_loop   = (const float*)d_in[4];
    const float* w_rel    = (const float*)d_in[5];
    const float* loop_rel = (const float*)d_in[6];
    const float* bias     = (const float*)d_in[7];
    const float* bn_gamma = (const float*)d_in[8];
    const float* bn_beta  = (const float*)d_in[9];
    const int*   edge_idx = (const int*)d_in[10];
    const int*   edge_typ = (const int*)d_in[11];

    const int* rowp = edge_idx;
    const int* colp = edge_idx + EE;

    float* hout = (float*)d_out;
    float* rout = (float*)d_out + (size_t)NN * D;

    cudaFuncSetAttribute(k_gemm_mma, cudaFuncAttributeMaxDynamicSharedMemorySize, SMEM_GEMM);

    void* zb_addr = nullptr;
    cudaGetSymbolAddress(&zb_addr, g_zb);
    cudaMemsetAsync(zb_addr, 0, sizeof(ZeroBlk));

    k_countmisc<<<GE_BLOCKS + MISC_BLOCKS, 256>>>(rowp, w_in, w_out, w_loop,
                                                  bias, loop_rel, r, w_rel, rout); // 1
    k_xconv<<<XCONV_BLOCKS, 256>>>(x, r);                                          // 2
    k_scanfill<<<NB_SCAN, SCAN_BS>>>(rowp, colp, edge_typ);                        // 3
    k_aggregate<<<(NN + 7) / 8, 256>>>();                                          // 4 (profiled)
    dim3 gg(2, GEMM_MBLK);
    k_gemm_mma<<<gg, 256, SMEM_GEMM>>>(hout);                                      // 5
    k_bn_finalize<<<1, D>>>(bn_gamma, bn_beta);                                    // 6
    k_bn_apply<<<(int)(((size_t)NN * D / 4 + 255) / 256), 256>>>(hout);            // 7
}

// round 15
// speedup vs baseline: 1.1174x; 1.0475x over previous
#include <cuda_runtime.h>
#include <cuda_fp16.h>
#include <math.h>
#include <stdint.h>

#define D      256
#define NN     100000
#define EE     1000000
#define HALF_E (EE / 2)
#define RR     474
#define SCAN_BS 1024
#define NB_SCAN ((NN + SCAN_BS - 1) / SCAN_BS)   // 98
#define BN_EPS 1e-5f

#define KTOT   768          // combined K: [pre_in | pre_out | x]
#define NKS    24           // 768 / 32 (k32 per stage)
#define GEMM_MBLK ((NN + 127) / 128)   // 782
#define GE_BLOCKS ((EE + 255) / 256)   // 3907
#define MISC_BLOCKS (KTOT + 1 + RR)    // 1243
#define XCONV_THREADS (NN * 32 + RR * 32)
#define XCONV_BLOCKS ((XCONV_THREADS + 255) / 256)

// SMEM stage: A (128 rows x 64B data + 16B pad) | B (128 x 80B)
#define ROWB    80
#define ASPL    (128 * ROWB)       // 10240
#define STAGE   (2 * ASPL)         // 20480
#define NSTAGE  3
#define SM_STATS (NSTAGE * STAGE)          // 61440
#define SMEM_GEMM (SM_STATS + 1024)        // 62464

// ---------------- static device scratch ----------------
struct ZeroBlk {
    int   cnt[NN];
    float colsum[D];
    float colsumsq[D];
    int   flag;
    int   total;
};
__device__ ZeroBlk g_zb;

__device__ __half g_A[(size_t)NN * KTOT];      // 153.6 MB, fp16
__device__ __half g_B[(size_t)D * KTOT];       // [n][k] fp16
__device__ __half g_xh[(size_t)NN * D];        // 51.2 MB, fp16 copy of x
__device__ __half g_rh[(size_t)RR * D];        // fp16 copy of r
__device__ int      g_start[NN];
__device__ int      g_cursor[NN];
__device__ unsigned g_epack[EE];   // mode<<31 | et<<17 | col
__device__ float    g_dinv[NN];
__device__ float    g_bias2[D];
__device__ float    g_scale[D];
__device__ float    g_shift[D];

// ---------------- helpers ----------------
__device__ __forceinline__ uint32_t smem_u32(const void* p) {
    uint32_t a;
    asm("{ .reg .u64 t; cvta.to.shared.u64 t, %1; cvt.u32.u64 %0, t; }" : "=r"(a) : "l"(p));
    return a;
}

#define CP_ASYNC16(dst, src, sz) \
    asm volatile("cp.async.cg.shared.global [%0], [%1], 16, %2;" \
        :: "r"(dst), "l"(src), "r"(sz) : "memory")
#define CP_COMMIT() asm volatile("cp.async.commit_group;" ::: "memory")
#define CP_WAIT2()  asm volatile("cp.async.wait_group 2;" ::: "memory")

#define LDMATRIX_X4(r0, r1, r2, r3, addr) \
    asm volatile("ldmatrix.sync.aligned.m8n8.x4.shared.b16 {%0,%1,%2,%3}, [%4];" \
        : "=r"(r0), "=r"(r1), "=r"(r2), "=r"(r3) : "r"(addr))

#define MMA16816F16(C, A, B0, B1) \
    asm volatile("mma.sync.aligned.m16n8k16.row.col.f32.f16.f16.f32 " \
        "{%0,%1,%2,%3}, {%4,%5,%6,%7}, {%8,%9}, {%0,%1,%2,%3};" \
        : "+f"((C)[0]), "+f"((C)[1]), "+f"((C)[2]), "+f"((C)[3]) \
        : "r"((A)[0]), "r"((A)[1]), "r"((A)[2]), "r"((A)[3]), "r"(B0), "r"(B1))

// convert 8 fp32 -> fp16 packed in uint4
__device__ __forceinline__ uint4 pack_half8(const float* v) {
    uint32_t h[4];
#pragma unroll
    for (int q = 0; q < 4; q++) {
        __half2 p = __floats2half2_rn(v[2 * q], v[2 * q + 1]);
        h[q] = *reinterpret_cast<uint32_t*>(&p);
    }
    return make_uint4(h[0], h[1], h[2], h[3]);
}

// ---------------- launch 1: edge count histogram + misc (fused) ----------------
__global__ void k_countmisc(const int* __restrict__ rowp,
                            const float* __restrict__ w_in,
                            const float* __restrict__ w_out,
                            const float* __restrict__ w_loop,
                            const float* __restrict__ bias,
                            const float* __restrict__ loop_rel,
                            const float* __restrict__ r,
                            const float* __restrict__ w_rel,
                            float* __restrict__ rout) {
    int b = blockIdx.x;
    if (b < GE_BLOCKS) {
        int e = b * 256 + threadIdx.x;
        if (e < EE) atomicAdd(&g_zb.cnt[rowp[e]], 1);
        return;
    }
    int mb = b - GE_BLOCKS;
    int n = threadIdx.x;
    if (n >= D) return;
    if (mb < KTOT) {                      // W transpose to fp16
        int k = mb;
        const float* W = (k < 256) ? w_in : (k < 512) ? w_out : w_loop;
        float v = W[(size_t)(k & 255) * D + n];
        g_B[(size_t)n * KTOT + k] = __float2half_rn(v);
    } else if (mb == KTOT) {              // bias2 = bias - loop_rel @ w_loop
        float acc = bias[n];
        for (int k = 0; k < D; k++)
            acc -= loop_rel[k] * w_loop[k * D + n];
        g_bias2[n] = acc;
    } else {                              // relgemm row
        int row = mb - KTOT - 1;
        const float* rr = r + (size_t)row * D;
        float acc = 0.f;
#pragma unroll 8
        for (int k = 0; k < D; k++)
            acc += rr[k] * w_rel[k * D + n];
        rout[(size_t)row * D + n] = acc;
    }
}

// ---------------- launch 2: x, r -> fp16 (x_h also seeds g_A cols [512,768)) ----------------
__global__ void k_xconv(const float* __restrict__ x, const float* __restrict__ r) {
    int gid = blockIdx.x * 256 + threadIdx.x;
    if (gid < NN * 32) {
        int row = gid >> 5, c8 = gid & 31;
        const float4* src = (const float4*)(x + (size_t)row * D + c8 * 8);
        float4 v0 = src[0], v1 = src[1];
        float v[8] = {v0.x, v0.y, v0.z, v0.w, v1.x, v1.y, v1.z, v1.w};
        uint4 hv = pack_half8(v);
        *(uint4*)(g_xh + (size_t)row * D + c8 * 8) = hv;
        *(uint4*)(g_A + (size_t)row * KTOT + 512 + c8 * 8) = hv;
    } else {
        int g2 = gid - NN * 32;
        if (g2 < RR * 32) {
            int row = g2 >> 5, c8 = g2 & 31;
            const float4* src = (const float4*)(r + (size_t)row * D + c8 * 8);
            float4 v0 = src[0], v1 = src[1];
            float v[8] = {v0.x, v0.y, v0.z, v0.w, v1.x, v1.y, v1.z, v1.w};
            *(uint4*)(g_rh + (size_t)row * D + c8 * 8) = pack_half8(v);
        }
    }
}

// ---------------- launch 3: scan + dinv + start/cursor + edge fill (fused) ----------------
__global__ void k_scanfill(const int* __restrict__ rowp,
                           const int* __restrict__ colp,
                           const int* __restrict__ etp) {
    __shared__ int s[SCAN_BS];
    __shared__ int base_sh;
    int t = threadIdx.x;
    int bid = blockIdx.x;
    int i = bid * SCAN_BS + t;
    int v = (i < NN) ? g_zb.cnt[i] : 0;
    if (i < NN) g_dinv[i] = (v > 0) ? rsqrtf((float)v) : 0.f;
    s[t] = v;
    __syncthreads();
    for (int off = 1; off < SCAN_BS; off <<= 1) {
        int a = (t >= off) ? s[t - off] : 0;
        __syncthreads();
        s[t] += a;
        __syncthreads();
    }
    int incl = s[t];
    if (t == 0) {
        int btot = s[SCAN_BS - 1];
        while (atomicAdd(&g_zb.flag, 0) != bid) {}
        __threadfence();
        int b = g_zb.total;
        g_zb.total = b + btot;
        __threadfence();
        atomicExch(&g_zb.flag, bid + 1);
        base_sh = b;
    }
    __syncthreads();
    if (i < NN) {
        int st = base_sh + incl - v;
        g_start[i] = st;
        g_cursor[i] = st;
    }
    if (t == 0) {
        while (atomicAdd(&g_zb.flag, 0) != NB_SCAN) {}
        base_sh = 0;
    }
    __syncthreads();
    __threadfence();
    int nthreads = NB_SCAN * SCAN_BS;
    for (int e = bid * SCAN_BS + t; e < EE; e += nthreads) {
        int pos = atomicAdd(&g_cursor[rowp[e]], 1);
        unsigned pk = ((e < HALF_E) ? 0u : 0x80000000u) |
                      ((unsigned)etp[e] << 17) | (unsigned)colp[e];
        g_epack[pos] = pk;
    }
}

// ---------------- launch 4 (profiled): aggregate, half2 regs + uniform branches ----------------
__global__ void k_aggregate() {
    int node = blockIdx.x * 8 + (threadIdx.x >> 5);
    if (node >= NN) return;
    int lane = threadIdx.x & 31;
    int base = lane * 8;
    size_t rb = (size_t)node * KTOT;

    __half2 zero = __float2half2_rn(0.f);
    __half2 ai0 = zero, ai1 = zero, ai2 = zero, ai3 = zero;
    __half2 ao0 = zero, ao1 = zero, ao2 = zero, ao3 = zero;

    int s = g_start[node];
    int c = g_zb.cnt[node];
    float di = g_dinv[node];
    int end = s + c;
    int p = s;

    for (; p + 2 <= end; p += 2) {
        unsigned pk0 = g_epack[p], pk1 = g_epack[p + 1];
        int cl0 = pk0 & 0x1FFFF, et0 = (pk0 >> 17) & 0x1FF;
        int cl1 = pk1 & 0x1FFFF, et1 = (pk1 >> 17) & 0x1FF;
        __half2 n0 = __float2half2_rn(di * g_dinv[cl0]);
        __half2 n1 = __float2half2_rn(di * g_dinv[cl1]);
        uint4 xa = *(const uint4*)(g_xh + (size_t)cl0 * D + base);
        uint4 ra = *(const uint4*)(g_rh + (size_t)et0 * D + base);
        uint4 xb = *(const uint4*)(g_xh + (size_t)cl1 * D + base);
        uint4 rv = *(const uint4*)(g_rh + (size_t)et1 * D + base);
        const __half2* xah = (const __half2*)&xa;
        const __half2* rah = (const __half2*)&ra;
        const __half2* xbh = (const __half2*)&xb;
        const __half2* rbh = (const __half2*)&rv;
        __half2 d00 = __hsub2(xah[0], rah[0]);
        __half2 d01 = __hsub2(xah[1], rah[1]);
        __half2 d02 = __hsub2(xah[2], rah[2]);
        __half2 d03 = __hsub2(xah[3], rah[3]);
        if (!(pk0 & 0x80000000u)) {
            ai0 = __hfma2(d00, n0, ai0);
            ai1 = __hfma2(d01, n0, ai1);
            ai2 = __hfma2(d02, n0, ai2);
            ai3 = __hfma2(d03, n0, ai3);
        } else {
            ao0 = __hfma2(d00, n0, ao0);
            ao1 = __hfma2(d01, n0, ao1);
            ao2 = __hfma2(d02, n0, ao2);
            ao3 = __hfma2(d03, n0, ao3);
        }
        __half2 d10 = __hsub2(xbh[0], rbh[0]);
        __half2 d11 = __hsub2(xbh[1], rbh[1]);
        __half2 d12 = __hsub2(xbh[2], rbh[2]);
        __half2 d13 = __hsub2(xbh[3], rbh[3]);
        if (!(pk1 & 0x80000000u)) {
            ai0 = __hfma2(d10, n1, ai0);
            ai1 = __hfma2(d11, n1, ai1);
            ai2 = __hfma2(d12, n1, ai2);
            ai3 = __hfma2(d13, n1, ai3);
        } else {
            ao0 = __hfma2(d10, n1, ao0);
            ao1 = __hfma2(d11, n1, ao1);
            ao2 = __hfma2(d12, n1, ao2);
            ao3 = __hfma2(d13, n1, ao3);
        }
    }
    if (p < end) {
        unsigned pk = g_epack[p];
        int cl = pk & 0x1FFFF, et = (pk >> 17) & 0x1FF;
        __half2 nrm = __float2half2_rn(di * g_dinv[cl]);
        uint4 xa = *(const uint4*)(g_xh + (size_t)cl * D + base);
        uint4 ra = *(const uint4*)(g_rh + (size_t)et * D + base);
        const __half2* xah = (const __half2*)&xa;
        const __half2* rah = (const __half2*)&ra;
        __half2 d00 = __hsub2(xah[0], rah[0]);
        __half2 d01 = __hsub2(xah[1], rah[1]);
        __half2 d02 = __hsub2(xah[2], rah[2]);
        __half2 d03 = __hsub2(xah[3], rah[3]);
        if (!(pk & 0x80000000u)) {
            ai0 = __hfma2(d00, nrm, ai0);
            ai1 = __hfma2(d01, nrm, ai1);
            ai2 = __hfma2(d02, nrm, ai2);
            ai3 = __hfma2(d03, nrm, ai3);
        } else {
            ao0 = __hfma2(d00, nrm, ao0);
            ao1 = __hfma2(d01, nrm, ao1);
            ao2 = __hfma2(d02, nrm, ao2);
            ao3 = __hfma2(d03, nrm, ao3);
        }
    }
    uint4 vin, vout;
    ((__half2*)&vin)[0] = ai0;  ((__half2*)&vin)[1] = ai1;
    ((__half2*)&vin)[2] = ai2;  ((__half2*)&vin)[3] = ai3;
    ((__half2*)&vout)[0] = ao0; ((__half2*)&vout)[1] = ao1;
    ((__half2*)&vout)[2] = ao2; ((__half2*)&vout)[3] = ao3;
    *(uint4*)(g_A + rb + base)       = vin;
    *(uint4*)(g_A + rb + 256 + base) = vout;
}

// ---------------- launch 5: mma.sync fp16 GEMM (M128 x N128, k32 stages) ----------------
__device__ __forceinline__ void load_stage(uint32_t sb, int buf, int kOff,
                                           int rowBase, int colBase, int tid) {
    uint32_t base = sb + buf * STAGE;
#pragma unroll
    for (int i = 0; i < 4; i++) {
        int c = tid + i * 256;
        int isB = c >> 9;
        int rem = c & 511;
        int row = rem >> 2, q = rem & 3;
        uint32_t dst = base + isB * ASPL + row * ROWB + q * 16;
        const __half* src;
        int sz = 16;
        if (!isB) {
            int gr = rowBase + row;
            if (gr >= NN) { gr = 0; sz = 0; }
            src = g_A + (size_t)gr * KTOT + kOff + q * 8;
        } else {
            int gc = colBase + row;
            src = g_B + (size_t)gc * KTOT + kOff + q * 8;
        }
        CP_ASYNC16(dst, (const void*)src, sz);
    }
}

__global__ void __launch_bounds__(256, 2)
k_gemm_mma(float* __restrict__ hout) {
    extern __shared__ char smem[];
    uint32_t sb = smem_u32(smem);
    int tid = threadIdx.x;
    int lane = tid & 31, wid = tid >> 5;
    int warp_m = wid & 1;
    int warp_n = wid >> 1;
    int colBase = blockIdx.x * 128;
    int rowBase = blockIdx.y * 128;

    float c[4][4][4];
#pragma unroll
    for (int i = 0; i < 4; i++)
#pragma unroll
        for (int j = 0; j < 4; j++)
#pragma unroll
            for (int q = 0; q < 4; q++) c[i][j][q] = 0.f;

#pragma unroll
    for (int s = 0; s < NSTAGE; s++) {
        load_stage(sb, s, s * 32, rowBase, colBase, tid);
        CP_COMMIT();
    }

    uint32_t a_off = (lane & 15) * ROWB + (lane >> 4) * 16;
    uint32_t b_off = (((lane >> 4) << 3) + (lane & 7)) * ROWB + ((lane >> 3) & 1) * 16;

    for (int it = 0; it < NKS; it++) {
        CP_WAIT2();
        __syncthreads();
        uint32_t st = sb + (it % 3) * STAGE;

#pragma unroll
        for (int ks2 = 0; ks2 < 2; ks2++) {
            uint32_t kb = ks2 * 32;
            uint32_t a[4][4];
#pragma unroll
            for (int mt = 0; mt < 4; mt++) {
                uint32_t addr = st + (warp_m * 64 + mt * 16) * ROWB + kb + a_off;
                LDMATRIX_X4(a[mt][0], a[mt][1], a[mt][2], a[mt][3], addr);
            }
            uint32_t b[2][4];
#pragma unroll
            for (int pr = 0; pr < 2; pr++) {
                uint32_t addr = st + ASPL + (warp_n * 32 + pr * 16) * ROWB + kb + b_off;
                LDMATRIX_X4(b[pr][0], b[pr][1], b[pr][2], b[pr][3], addr);
            }
#pragma unroll
            for (int mt = 0; mt < 4; mt++)
#pragma unroll
                for (int nt = 0; nt < 4; nt++) {
                    int pr = nt >> 1, ix = (nt & 1) * 2;
                    MMA16816F16(c[mt][nt], a[mt], b[pr][ix], b[pr][ix + 1]);
                }
        }
        __syncthreads();
        if (it + 3 < NKS)
            load_stage(sb, it % 3, (it + 3) * 32, rowBase, colBase, tid);
        CP_COMMIT();
    }

    // ---- epilogue: write hout (fp32) + per-CTA column stats ----
    float* cs  = (float*)(smem + SM_STATS);
    float* css = (float*)(smem + SM_STATS) + 128;
    __syncthreads();
    ((float*)(smem + SM_STATS))[tid] = 0.f;
    __syncthreads();

#pragma unroll
    for (int nt = 0; nt < 4; nt++) {
        int lcol = warp_n * 32 + nt * 8 + (lane & 3) * 2;
        int col = colBase + lcol;
        float b0 = g_bias2[col], b1 = g_bias2[col + 1];
        float s0 = 0.f, s1 = 0.f, q0 = 0.f, q1 = 0.f;
#pragma unroll
        for (int mt = 0; mt < 4; mt++) {
            int row = rowBase + warp_m * 64 + mt * 16 + (lane >> 2);
            if (row < NN) {
                float v0 = c[mt][nt][0] + b0, v1 = c[mt][nt][1] + b1;
                *(float2*)(hout + (size_t)row * D + col) = make_float2(v0, v1);
                s0 += v0; s1 += v1; q0 += v0 * v0; q1 += v1 * v1;
            }
            int row2 = row + 8;
            if (row2 < NN) {
                float v0 = c[mt][nt][2] + b0, v1 = c[mt][nt][3] + b1;
                *(float2*)(hout + (size_t)row2 * D + col) = make_float2(v0, v1);
                s0 += v0; s1 += v1; q0 += v0 * v0; q1 += v1 * v1;
            }
        }
        atomicAdd(&cs[lcol], s0);
        atomicAdd(&cs[lcol + 1], s1);
        atomicAdd(&css[lcol], q0);
        atomicAdd(&css[lcol + 1], q1);
    }
    __syncthreads();
    if (tid < 128) atomicAdd(&g_zb.colsum[colBase + tid], cs[tid]);
    else           atomicAdd(&g_zb.colsumsq[colBase + (tid - 128)], css[tid - 128]);
}

// ---------------- BN finalize / apply ----------------
__global__ void k_bn_finalize(const float* __restrict__ gamma,
                              const float* __restrict__ beta) {
    int c = threadIdx.x;
    float mean = g_zb.colsum[c] / (float)NN;
    float var = g_zb.colsumsq[c] / (float)NN - mean * mean;
    float inv = rsqrtf(var + BN_EPS);
    float sc = gamma[c] * inv;
    g_scale[c] = sc;
    g_shift[c] = beta[c] - mean * sc;
}
__global__ void k_bn_apply(float* __restrict__ hout) {
    size_t i4 = (size_t)blockIdx.x * blockDim.x + threadIdx.x;
    size_t total4 = (size_t)NN * D / 4;
    if (i4 < total4) {
        int c = (int)((i4 & 63) * 4);
        float4 v = *(float4*)(hout + i4 * 4);
        v.x = tanhf(v.x * g_scale[c + 0] + g_shift[c + 0]);
        v.y = tanhf(v.y * g_scale[c + 1] + g_shift[c + 1]);
        v.z = tanhf(v.z * g_scale[c + 2] + g_shift[c + 2]);
        v.w = tanhf(v.w * g_scale[c + 3] + g_shift[c + 3]);
        *(float4*)(hout + i4 * 4) = v;
    }
}

// ---------------- launch ----------------
extern "C" void kernel_launch(void* const* d_in, const int* in_sizes, int n_in,
                              void* d_out, int out_size) {
    const float* x        = (const float*)d_in[0];
    const float* r        = (const float*)d_in[1];
    const float* w_in     = (const float*)d_in[2];
    const float* w_out    = (const float*)d_in[3];
    const float* w_loop   = (const float*)d_in[4];
    const float* w_rel    = (const float*)d_in[5];
    const float* loop_rel = (const float*)d_in[6];
    const float* bias     = (const float*)d_in[7];
    const float* bn_gamma = (const float*)d_in[8];
    const float* bn_beta  = (const float*)d_in[9];
    const int*   edge_idx = (const int*)d_in[10];
    const int*   edge_typ = (const int*)d_in[11];

    const int* rowp = edge_idx;
    const int* colp = edge_idx + EE;

    float* hout = (float*)d_out;
    float* rout = (float*)d_out + (size_t)NN * D;

    cudaFuncSetAttribute(k_gemm_mma, cudaFuncAttributeMaxDynamicSharedMemorySize, SMEM_GEMM);

    void* zb_addr = nullptr;
    cudaGetSymbolAddress(&zb_addr, g_zb);
    cudaMemsetAsync(zb_addr, 0, sizeof(ZeroBlk));

    k_countmisc<<<GE_BLOCKS + MISC_BLOCKS, 256>>>(rowp, w_in, w_out, w_loop,
                                                  bias, loop_rel, r, w_rel, rout); // 1
    k_xconv<<<XCONV_BLOCKS, 256>>>(x, r);                                          // 2
    k_scanfill<<<NB_SCAN, SCAN_BS>>>(rowp, colp, edge_typ);                        // 3
    k_aggregate<<<(NN + 7) / 8, 256>>>();                                          // 4 (profiled)
    dim3 gg(2, GEMM_MBLK);
    k_gemm_mma<<<gg, 256, SMEM_GEMM>>>(hout);                                      // 5
    k_bn_finalize<<<1, D>>>(bn_gamma, bn_beta);                                    // 6
    k_bn_apply<<<(int)(((size_t)NN * D / 4 + 255) / 256), 256>>>(hout);            // 7
}

// round 16
// speedup vs baseline: 1.1281x; 1.0096x over previous
#include <cuda_runtime.h>
#include <cuda_fp16.h>
#include <math.h>
#include <stdint.h>

#define D      256
#define NN     100000
#define EE     1000000
#define HALF_E (EE / 2)
#define RR     474
#define SCAN_BS 1024
#define NB_SCAN ((NN + SCAN_BS - 1) / SCAN_BS)   // 98
#define BN_EPS 1e-5f

#define KTOT   768          // combined K: [pre_in | pre_out | x]
#define NKS    24           // 768 / 32 (k32 per stage)
#define GEMM_MBLK ((NN + 127) / 128)   // 782
#define GE_BLOCKS ((EE + 255) / 256)   // 3907
#define MISC_BLOCKS (KTOT + 1 + RR)    // 1243
#define XCONV_BLOCKS ((NN * 32 + RR * 32 + 255) / 256)

// SMEM stage: A (128 rows x 64B data + 16B pad) | B (128 x 80B)
#define ROWB    80
#define ASPL    (128 * ROWB)       // 10240
#define STAGE   (2 * ASPL)         // 20480
#define NSTAGE  3
#define SM_STATS (NSTAGE * STAGE)          // 61440
#define SMEM_GEMM (SM_STATS + 1024)        // 62464

// ---------------- static device scratch ----------------
struct ZeroBlk {
    int   cnt[NN];
    float colsum[D];
    float colsumsq[D];
    int   flag;
    int   total;
};
__device__ ZeroBlk g_zb;

__device__ __half g_A[(size_t)NN * KTOT];      // 153.6 MB, fp16
__device__ __half g_B[(size_t)D * KTOT];       // [n][k] fp16
__device__ __half g_xh[(size_t)NN * D];        // 51.2 MB, fp16 copy of x
__device__ __half g_rh[(size_t)RR * D];        // fp16 copy of r
__device__ int      g_start[NN];
__device__ int      g_cursor[NN];
__device__ unsigned g_epack[EE];   // mode<<31 | et<<17 | col
__device__ float    g_dinv[NN];
__device__ float    g_bias2[D];
__device__ float    g_scale[D];
__device__ float    g_shift[D];

// ---------------- helpers ----------------
__device__ __forceinline__ uint32_t smem_u32(const void* p) {
    uint32_t a;
    asm("{ .reg .u64 t; cvta.to.shared.u64 t, %1; cvt.u32.u64 %0, t; }" : "=r"(a) : "l"(p));
    return a;
}

#define CP_ASYNC16(dst, src, sz) \
    asm volatile("cp.async.cg.shared.global [%0], [%1], 16, %2;" \
        :: "r"(dst), "l"(src), "r"(sz) : "memory")
#define CP_COMMIT() asm volatile("cp.async.commit_group;" ::: "memory")
#define CP_WAIT2()  asm volatile("cp.async.wait_group 2;" ::: "memory")

#define LDMATRIX_X4(r0, r1, r2, r3, addr) \
    asm volatile("ldmatrix.sync.aligned.m8n8.x4.shared.b16 {%0,%1,%2,%3}, [%4];" \
        : "=r"(r0), "=r"(r1), "=r"(r2), "=r"(r3) : "r"(addr))

#define MMA16816F16(C, A, B0, B1) \
    asm volatile("mma.sync.aligned.m16n8k16.row.col.f32.f16.f16.f32 " \
        "{%0,%1,%2,%3}, {%4,%5,%6,%7}, {%8,%9}, {%0,%1,%2,%3};" \
        : "+f"((C)[0]), "+f"((C)[1]), "+f"((C)[2]), "+f"((C)[3]) \
        : "r"((A)[0]), "r"((A)[1]), "r"((A)[2]), "r"((A)[3]), "r"(B0), "r"(B1))

// convert 8 fp32 -> fp16 packed in uint4
__device__ __forceinline__ uint4 pack_half8(const float* v) {
    uint32_t h[4];
#pragma unroll
    for (int q = 0; q < 4; q++) {
        __half2 p = __floats2half2_rn(v[2 * q], v[2 * q + 1]);
        h[q] = *reinterpret_cast<uint32_t*>(&p);
    }
    return make_uint4(h[0], h[1], h[2], h[3]);
}

// ---------------- launch 1: histogram + misc + x/r fp16 convert (fused) ----------------
__global__ void k_countmisc(const int* __restrict__ rowp,
                            const float* __restrict__ x,
                            const float* __restrict__ w_in,
                            const float* __restrict__ w_out,
                            const float* __restrict__ w_loop,
                            const float* __restrict__ bias,
                            const float* __restrict__ loop_rel,
                            const float* __restrict__ r,
                            const float* __restrict__ w_rel,
                            float* __restrict__ rout) {
    int b = blockIdx.x;
    if (b < GE_BLOCKS) {
        int e = b * 256 + threadIdx.x;
        if (e < EE) atomicAdd(&g_zb.cnt[rowp[e]], 1);
        return;
    }
    if (b < GE_BLOCKS + MISC_BLOCKS) {
        int mb = b - GE_BLOCKS;
        int n = threadIdx.x;
        if (n >= D) return;
        if (mb < KTOT) {                      // W transpose to fp16
            int k = mb;
            const float* W = (k < 256) ? w_in : (k < 512) ? w_out : w_loop;
            float v = W[(size_t)(k & 255) * D + n];
            g_B[(size_t)n * KTOT + k] = __float2half_rn(v);
        } else if (mb == KTOT) {              // bias2 = bias - loop_rel @ w_loop
            float acc = bias[n];
            for (int k = 0; k < D; k++)
                acc -= loop_rel[k] * w_loop[k * D + n];
            g_bias2[n] = acc;
        } else {                              // relgemm row
            int row = mb - KTOT - 1;
            const float* rr = r + (size_t)row * D;
            float acc = 0.f;
#pragma unroll 8
            for (int k = 0; k < D; k++)
                acc += rr[k] * w_rel[k * D + n];
            rout[(size_t)row * D + n] = acc;
        }
        return;
    }
    // x / r -> fp16; x_h also seeds g_A cols [512, 768)
    int gid = (b - GE_BLOCKS - MISC_BLOCKS) * 256 + threadIdx.x;
    if (gid < NN * 32) {
        int row = gid >> 5, c8 = gid & 31;
        const float4* src = (const float4*)(x + (size_t)row * D + c8 * 8);
        float4 v0 = src[0], v1 = src[1];
        float v[8] = {v0.x, v0.y, v0.z, v0.w, v1.x, v1.y, v1.z, v1.w};
        uint4 hv = pack_half8(v);
        *(uint4*)(g_xh + (size_t)row * D + c8 * 8) = hv;
        *(uint4*)(g_A + (size_t)row * KTOT + 512 + c8 * 8) = hv;
    } else {
        int g2 = gid - NN * 32;
        if (g2 < RR * 32) {
            int row = g2 >> 5, c8 = g2 & 31;
            const float4* src = (const float4*)(r + (size_t)row * D + c8 * 8);
            float4 v0 = src[0], v1 = src[1];
            float v[8] = {v0.x, v0.y, v0.z, v0.w, v1.x, v1.y, v1.z, v1.w};
            *(uint4*)(g_rh + (size_t)row * D + c8 * 8) = pack_half8(v);
        }
    }
}

// ---------------- launch 2: scan + dinv + start/cursor + edge fill (fused) ----------------
__global__ void k_scanfill(const int* __restrict__ rowp,
                           const int* __restrict__ colp,
                           const int* __restrict__ etp) {
    __shared__ int s[SCAN_BS];
    __shared__ int base_sh;
    int t = threadIdx.x;
    int bid = blockIdx.x;
    int i = bid * SCAN_BS + t;
    int v = (i < NN) ? g_zb.cnt[i] : 0;
    if (i < NN) g_dinv[i] = (v > 0) ? rsqrtf((float)v) : 0.f;
    s[t] = v;
    __syncthreads();
    for (int off = 1; off < SCAN_BS; off <<= 1) {
        int a = (t >= off) ? s[t - off] : 0;
        __syncthreads();
        s[t] += a;
        __syncthreads();
    }
    int incl = s[t];
    if (t == 0) {
        int btot = s[SCAN_BS - 1];
        while (atomicAdd(&g_zb.flag, 0) != bid) {}
        __threadfence();
        int b = g_zb.total;
        g_zb.total = b + btot;
        __threadfence();
        atomicExch(&g_zb.flag, bid + 1);
        base_sh = b;
    }
    __syncthreads();
    if (i < NN) {
        int st = base_sh + incl - v;
        g_start[i] = st;
        g_cursor[i] = st;
    }
    if (t == 0) {
        while (atomicAdd(&g_zb.flag, 0) != NB_SCAN) {}
        base_sh = 0;
    }
    __syncthreads();
    __threadfence();
    int nthreads = NB_SCAN * SCAN_BS;
    for (int e = bid * SCAN_BS + t; e < EE; e += nthreads) {
        int pos = atomicAdd(&g_cursor[rowp[e]], 1);
        unsigned pk = ((e < HALF_E) ? 0u : 0x80000000u) |
                      ((unsigned)etp[e] << 17) | (unsigned)colp[e];
        g_epack[pos] = pk;
    }
}

// ---------------- launch 3: aggregate, half2 regs + uniform branches ----------------
__global__ void k_aggregate() {
    int node = blockIdx.x * 8 + (threadIdx.x >> 5);
    if (node >= NN) return;
    int lane = threadIdx.x & 31;
    int base = lane * 8;
    size_t rb = (size_t)node * KTOT;

    __half2 zero = __float2half2_rn(0.f);
    __half2 ai0 = zero, ai1 = zero, ai2 = zero, ai3 = zero;
    __half2 ao0 = zero, ao1 = zero, ao2 = zero, ao3 = zero;

    int s = g_start[node];
    int c = g_zb.cnt[node];
    float di = g_dinv[node];
    int end = s + c;
    int p = s;

    for (; p + 2 <= end; p += 2) {
        unsigned pk0 = g_epack[p], pk1 = g_epack[p + 1];
        int cl0 = pk0 & 0x1FFFF, et0 = (pk0 >> 17) & 0x1FF;
        int cl1 = pk1 & 0x1FFFF, et1 = (pk1 >> 17) & 0x1FF;
        __half2 n0 = __float2half2_rn(di * g_dinv[cl0]);
        __half2 n1 = __float2half2_rn(di * g_dinv[cl1]);
        uint4 xa = *(const uint4*)(g_xh + (size_t)cl0 * D + base);
        uint4 ra = *(const uint4*)(g_rh + (size_t)et0 * D + base);
        uint4 xb = *(const uint4*)(g_xh + (size_t)cl1 * D + base);
        uint4 rv = *(const uint4*)(g_rh + (size_t)et1 * D + base);
        const __half2* xah = (const __half2*)&xa;
        const __half2* rah = (const __half2*)&ra;
        const __half2* xbh = (const __half2*)&xb;
        const __half2* rbh = (const __half2*)&rv;
        __half2 d00 = __hsub2(xah[0], rah[0]);
        __half2 d01 = __hsub2(xah[1], rah[1]);
        __half2 d02 = __hsub2(xah[2], rah[2]);
        __half2 d03 = __hsub2(xah[3], rah[3]);
        if (!(pk0 & 0x80000000u)) {
            ai0 = __hfma2(d00, n0, ai0);
            ai1 = __hfma2(d01, n0, ai1);
            ai2 = __hfma2(d02, n0, ai2);
            ai3 = __hfma2(d03, n0, ai3);
        } else {
            ao0 = __hfma2(d00, n0, ao0);
            ao1 = __hfma2(d01, n0, ao1);
            ao2 = __hfma2(d02, n0, ao2);
            ao3 = __hfma2(d03, n0, ao3);
        }
        __half2 d10 = __hsub2(xbh[0], rbh[0]);
        __half2 d11 = __hsub2(xbh[1], rbh[1]);
        __half2 d12 = __hsub2(xbh[2], rbh[2]);
        __half2 d13 = __hsub2(xbh[3], rbh[3]);
        if (!(pk1 & 0x80000000u)) {
            ai0 = __hfma2(d10, n1, ai0);
            ai1 = __hfma2(d11, n1, ai1);
            ai2 = __hfma2(d12, n1, ai2);
            ai3 = __hfma2(d13, n1, ai3);
        } else {
            ao0 = __hfma2(d10, n1, ao0);
            ao1 = __hfma2(d11, n1, ao1);
            ao2 = __hfma2(d12, n1, ao2);
            ao3 = __hfma2(d13, n1, ao3);
        }
    }
    if (p < end) {
        unsigned pk = g_epack[p];
        int cl = pk & 0x1FFFF, et = (pk >> 17) & 0x1FF;
        __half2 nrm = __float2half2_rn(di * g_dinv[cl]);
        uint4 xa = *(const uint4*)(g_xh + (size_t)cl * D + base);
        uint4 ra = *(const uint4*)(g_rh + (size_t)et * D + base);
        const __half2* xah = (const __half2*)&xa;
        const __half2* rah = (const __half2*)&ra;
        __half2 d00 = __hsub2(xah[0], rah[0]);
        __half2 d01 = __hsub2(xah[1], rah[1]);
        __half2 d02 = __hsub2(xah[2], rah[2]);
        __half2 d03 = __hsub2(xah[3], rah[3]);
        if (!(pk & 0x80000000u)) {
            ai0 = __hfma2(d00, nrm, ai0);
            ai1 = __hfma2(d01, nrm, ai1);
            ai2 = __hfma2(d02, nrm, ai2);
            ai3 = __hfma2(d03, nrm, ai3);
        } else {
            ao0 = __hfma2(d00, nrm, ao0);
            ao1 = __hfma2(d01, nrm, ao1);
            ao2 = __hfma2(d02, nrm, ao2);
            ao3 = __hfma2(d03, nrm, ao3);
        }
    }
    uint4 vin, vout;
    ((__half2*)&vin)[0] = ai0;  ((__half2*)&vin)[1] = ai1;
    ((__half2*)&vin)[2] = ai2;  ((__half2*)&vin)[3] = ai3;
    ((__half2*)&vout)[0] = ao0; ((__half2*)&vout)[1] = ao1;
    ((__half2*)&vout)[2] = ao2; ((__half2*)&vout)[3] = ao3;
    *(uint4*)(g_A + rb + base)       = vin;
    *(uint4*)(g_A + rb + 256 + base) = vout;
}

// ---------------- launch 4 (profiled): mma.sync fp16 GEMM, hoisted cp.async addressing ----------------
#define LOADSTAGE(buf, kOff) do { \
    uint32_t bb = sb + (buf) * STAGE + dst0; \
    CP_ASYNC16(bb,                    srcA0 + (kOff), sz0); \
    CP_ASYNC16(bb + 64 * ROWB,        srcA1 + (kOff), sz1); \
    CP_ASYNC16(bb + ASPL,             srcB0 + (kOff), 16); \
    CP_ASYNC16(bb + ASPL + 64 * ROWB, srcB1 + (kOff), 16); \
} while (0)

__global__ void __launch_bounds__(256, 2)
k_gemm_mma(float* __restrict__ hout) {
    extern __shared__ char smem[];
    uint32_t sb = smem_u32(smem);
    int tid = threadIdx.x;
    int lane = tid & 31, wid = tid >> 5;
    int warp_m = wid & 1;
    int warp_n = wid >> 1;
    int colBase = blockIdx.x * 128;
    int rowBase = blockIdx.y * 128;

    // hoisted load descriptors: chunks 0,1 = A rows (row0, row0+64); 2,3 = B rows
    int row0 = tid >> 2, q = tid & 3;
    uint32_t dst0 = row0 * ROWB + q * 16;
    int gr0 = rowBase + row0;
    int gr1 = gr0 + 64;
    int sz0 = (gr0 < NN) ? 16 : 0;
    int sz1 = (gr1 < NN) ? 16 : 0;
    const __half* srcA0 = g_A + (size_t)(sz0 ? gr0 : 0) * KTOT + q * 8;
    const __half* srcA1 = g_A + (size_t)(sz1 ? gr1 : 0) * KTOT + q * 8;
    const __half* srcB0 = g_B + (size_t)(colBase + row0) * KTOT + q * 8;
    const __half* srcB1 = srcB0 + (size_t)64 * KTOT;

    float c[4][4][4];
#pragma unroll
    for (int i = 0; i < 4; i++)
#pragma unroll
        for (int j = 0; j < 4; j++)
#pragma unroll
            for (int qq = 0; qq < 4; qq++) c[i][j][qq] = 0.f;

#pragma unroll
    for (int s = 0; s < NSTAGE; s++) {
        LOADSTAGE(s, s * 32);
        CP_COMMIT();
    }

    uint32_t a_off = (lane & 15) * ROWB + (lane >> 4) * 16;
    uint32_t b_off = (((lane >> 4) << 3) + (lane & 7)) * ROWB + ((lane >> 3) & 1) * 16;

    for (int it = 0; it < NKS; it++) {
        CP_WAIT2();
        __syncthreads();
        uint32_t st = sb + (it % 3) * STAGE;

#pragma unroll
        for (int ks2 = 0; ks2 < 2; ks2++) {
            uint32_t kb = ks2 * 32;
            uint32_t a[4][4];
#pragma unroll
            for (int mt = 0; mt < 4; mt++) {
                uint32_t addr = st + (warp_m * 64 + mt * 16) * ROWB + kb + a_off;
                LDMATRIX_X4(a[mt][0], a[mt][1], a[mt][2], a[mt][3], addr);
            }
            uint32_t b[2][4];
#pragma unroll
            for (int pr = 0; pr < 2; pr++) {
                uint32_t addr = st + ASPL + (warp_n * 32 + pr * 16) * ROWB + kb + b_off;
                LDMATRIX_X4(b[pr][0], b[pr][1], b[pr][2], b[pr][3], addr);
            }
#pragma unroll
            for (int mt = 0; mt < 4; mt++)
#pragma unroll
                for (int nt = 0; nt < 4; nt++) {
                    int pr = nt >> 1, ix = (nt & 1) * 2;
                    MMA16816F16(c[mt][nt], a[mt], b[pr][ix], b[pr][ix + 1]);
                }
        }
        __syncthreads();
        if (it + 3 < NKS) {
            LOADSTAGE(it % 3, (it + 3) * 32);
        }
        CP_COMMIT();
    }

    // ---- epilogue: write hout (fp32) + per-CTA column stats ----
    float* cs  = (float*)(smem + SM_STATS);
    float* css = (float*)(smem + SM_STATS) + 128;
    __syncthreads();
    ((float*)(smem + SM_STATS))[tid] = 0.f;
    __syncthreads();

#pragma unroll
    for (int nt = 0; nt < 4; nt++) {
        int lcol = warp_n * 32 + nt * 8 + (lane & 3) * 2;
        int col = colBase + lcol;
        float b0 = g_bias2[col], b1 = g_bias2[col + 1];
        float s0 = 0.f, s1 = 0.f, q0 = 0.f, q1 = 0.f;
#pragma unroll
        for (int mt = 0; mt < 4; mt++) {
            int row = rowBase + warp_m * 64 + mt * 16 + (lane >> 2);
            if (row < NN) {
                float v0 = c[mt][nt][0] + b0, v1 = c[mt][nt][1] + b1;
                *(float2*)(hout + (size_t)row * D + col) = make_float2(v0, v1);
                s0 += v0; s1 += v1; q0 += v0 * v0; q1 += v1 * v1;
            }
            int row2 = row + 8;
            if (row2 < NN) {
                float v0 = c[mt][nt][2] + b0, v1 = c[mt][nt][3] + b1;
                *(float2*)(hout + (size_t)row2 * D + col) = make_float2(v0, v1);
                s0 += v0; s1 += v1; q0 += v0 * v0; q1 += v1 * v1;
            }
        }
        atomicAdd(&cs[lcol], s0);
        atomicAdd(&cs[lcol + 1], s1);
        atomicAdd(&css[lcol], q0);
        atomicAdd(&css[lcol + 1], q1);
    }
    __syncthreads();
    if (tid < 128) atomicAdd(&g_zb.colsum[colBase + tid], cs[tid]);
    else           atomicAdd(&g_zb.colsumsq[colBase + (tid - 128)], css[tid - 128]);
}

// ---------------- BN finalize / apply ----------------
__global__ void k_bn_finalize(const float* __restrict__ gamma,
                              const float* __restrict__ beta) {
    int c = threadIdx.x;
    float mean = g_zb.colsum[c] / (float)NN;
    float var = g_zb.colsumsq[c] / (float)NN - mean * mean;
    float inv = rsqrtf(var + BN_EPS);
    float sc = gamma[c] * inv;
    g_scale[c] = sc;
    g_shift[c] = beta[c] - mean * sc;
}
__global__ void k_bn_apply(float* __restrict__ hout) {
    size_t i4 = (size_t)blockIdx.x * blockDim.x + threadIdx.x;
    size_t total4 = (size_t)NN * D / 4;
    if (i4 < total4) {
        int c = (int)((i4 & 63) * 4);
        float4 v = *(float4*)(hout + i4 * 4);
        v.x = tanhf(v.x * g_scale[c + 0] + g_shift[c + 0]);
        v.y = tanhf(v.y * g_scale[c + 1] + g_shift[c + 1]);
        v.z = tanhf(v.z * g_scale[c + 2] + g_shift[c + 2]);
        v.w = tanhf(v.w * g_scale[c + 3] + g_shift[c + 3]);
        *(float4*)(hout + i4 * 4) = v;
    }
}

// ---------------- launch ----------------
extern "C" void kernel_launch(void* const* d_in, const int* in_sizes, int n_in,
                              void* d_out, int out_size) {
    const float* x        = (const float*)d_in[0];
    const float* r        = (const float*)d_in[1];
    const float* w_in     = (const float*)d_in[2];
    const float* w_out    = (const float*)d_in[3];
    const float* w_loop   = (const float*)d_in[4];
    const float* w_rel    = (const float*)d_in[5];
    const float* loop_rel = (const float*)d_in[6];
    const float* bias     = (const float*)d_in[7];
    const float* bn_gamma = (const float*)d_in[8];
    const float* bn_beta  = (const float*)d_in[9];
    const int*   edge_idx = (const int*)d_in[10];
    const int*   edge_typ = (const int*)d_in[11];

    const int* rowp = edge_idx;
    const int* colp = edge_idx + EE;

    float* hout = (float*)d_out;
    float* rout = (float*)d_out + (size_t)NN * D;

    cudaFuncSetAttribute(k_gemm_mma, cudaFuncAttributeMaxDynamicSharedMemorySize, SMEM_GEMM);

    void* zb_addr = nullptr;
    cudaGetSymbolAddress(&zb_addr, g_zb);
    cudaMemsetAsync(zb_addr, 0, sizeof(ZeroBlk));

    k_countmisc<<<GE_BLOCKS + MISC_BLOCKS + XCONV_BLOCKS, 256>>>(
        rowp, x, w_in, w_out, w_loop, bias, loop_rel, r, w_rel, rout);      // 1
    k_scanfill<<<NB_SCAN, SCAN_BS>>>(rowp, colp, edge_typ);                 // 2
    k_aggregate<<<(NN + 7) / 8, 256>>>();                                   // 3
    dim3 gg(2, GEMM_MBLK);
    k_gemm_mma<<<gg, 256, SMEM_GEMM>>>(hout);                               // 4 (profiled)
    k_bn_finalize<<<1, D>>>(bn_gamma, bn_beta);                             // 5
    k_bn_apply<<<(int)(((size_t)NN * D / 4 + 255) / 256), 256>>>(hout);     // 6
}

// round 17
// speedup vs baseline: 1.1543x; 1.0232x over previous
#include <cuda_runtime.h>
#include <cuda_fp16.h>
#include <math.h>
#include <stdint.h>

#define D      256
#define NN     100000
#define EE     1000000
#define HALF_E (EE / 2)
#define RR     474
#define SCAN_BS 1024
#define NB_SCAN ((NN + SCAN_BS - 1) / SCAN_BS)   // 98
#define BN_EPS 1e-5f

#define KTOT   768          // combined K: [pre_in | pre_out | x]
#define NKS    24           // 768 / 32 (k32 per stage)
#define GEMM_MBLK ((NN + 127) / 128)   // 782
#define GE_BLOCKS ((EE + 255) / 256)   // 3907
#define MISC_BLOCKS (KTOT + 1 + RR)    // 1243
#define XCONV_BLOCKS ((NN * 32 + RR * 32 + 255) / 256)

// SMEM stage: A (128 rows x 64B data + 16B pad) | B (128 x 80B)
#define ROWB    80
#define ASPL    (128 * ROWB)       // 10240
#define STAGE   (2 * ASPL)         // 20480
#define NSTAGE  4
#define SM_STATS (NSTAGE * STAGE)          // 81920
#define SMEM_GEMM (SM_STATS + 1024)        // 82944

// ---------------- static device scratch ----------------
struct ZeroBlk {
    int   cnt[NN];
    float colsum[D];
    float colsumsq[D];
    int   flag;
    int   total;
};
__device__ ZeroBlk g_zb;

__device__ __half g_A[(size_t)NN * KTOT];      // 153.6 MB, fp16
__device__ __half g_B[(size_t)D * KTOT];       // [n][k] fp16
__device__ __half g_xh[(size_t)NN * D];        // 51.2 MB, fp16 copy of x
__device__ __half g_rh[(size_t)RR * D];        // fp16 copy of r
__device__ int      g_start[NN];
__device__ int      g_cursor[NN];
__device__ unsigned g_epack[EE];   // mode<<31 | et<<17 | col
__device__ float    g_dinv[NN];
__device__ float    g_bias2[D];
__device__ float    g_scale[D];
__device__ float    g_shift[D];

// ---------------- helpers ----------------
__device__ __forceinline__ uint32_t smem_u32(const void* p) {
    uint32_t a;
    asm("{ .reg .u64 t; cvta.to.shared.u64 t, %1; cvt.u32.u64 %0, t; }" : "=r"(a) : "l"(p));
    return a;
}

#define CP_ASYNC16(dst, src, sz) \
    asm volatile("cp.async.cg.shared.global [%0], [%1], 16, %2;" \
        :: "r"(dst), "l"(src), "r"(sz) : "memory")
#define CP_COMMIT() asm volatile("cp.async.commit_group;" ::: "memory")
#define CP_WAIT2()  asm volatile("cp.async.wait_group 2;" ::: "memory")

#define LDMATRIX_X4(r0, r1, r2, r3, addr) \
    asm volatile("ldmatrix.sync.aligned.m8n8.x4.shared.b16 {%0,%1,%2,%3}, [%4];" \
        : "=r"(r0), "=r"(r1), "=r"(r2), "=r"(r3) : "r"(addr))

#define MMA16816F16(C, A, B0, B1) \
    asm volatile("mma.sync.aligned.m16n8k16.row.col.f32.f16.f16.f32 " \
        "{%0,%1,%2,%3}, {%4,%5,%6,%7}, {%8,%9}, {%0,%1,%2,%3};" \
        : "+f"((C)[0]), "+f"((C)[1]), "+f"((C)[2]), "+f"((C)[3]) \
        : "r"((A)[0]), "r"((A)[1]), "r"((A)[2]), "r"((A)[3]), "r"(B0), "r"(B1))

// convert 8 fp32 -> fp16 packed in uint4
__device__ __forceinline__ uint4 pack_half8(const float* v) {
    uint32_t h[4];
#pragma unroll
    for (int q = 0; q < 4; q++) {
        __half2 p = __floats2half2_rn(v[2 * q], v[2 * q + 1]);
        h[q] = *reinterpret_cast<uint32_t*>(&p);
    }
    return make_uint4(h[0], h[1], h[2], h[3]);
}

// ---------------- launch 1: histogram + misc + x/r fp16 convert (fused) ----------------
__global__ void k_countmisc(const int* __restrict__ rowp,
                            const float* __restrict__ x,
                            const float* __restrict__ w_in,
                            const float* __restrict__ w_out,
                            const float* __restrict__ w_loop,
                            const float* __restrict__ bias,
                            const float* __restrict__ loop_rel,
                            const float* __restrict__ r,
                            const float* __restrict__ w_rel,
                            float* __restrict__ rout) {
    int b = blockIdx.x;
    if (b < GE_BLOCKS) {
        int e = b * 256 + threadIdx.x;
        if (e < EE) atomicAdd(&g_zb.cnt[rowp[e]], 1);
        return;
    }
    if (b < GE_BLOCKS + MISC_BLOCKS) {
        int mb = b - GE_BLOCKS;
        int n = threadIdx.x;
        if (n >= D) return;
        if (mb < KTOT) {                      // W transpose to fp16
            int k = mb;
            const float* W = (k < 256) ? w_in : (k < 512) ? w_out : w_loop;
            float v = W[(size_t)(k & 255) * D + n];
            g_B[(size_t)n * KTOT + k] = __float2half_rn(v);
        } else if (mb == KTOT) {              // bias2 = bias - loop_rel @ w_loop
            float acc = bias[n];
            for (int k = 0; k < D; k++)
                acc -= loop_rel[k] * w_loop[k * D + n];
            g_bias2[n] = acc;
        } else {                              // relgemm row
            int row = mb - KTOT - 1;
            const float* rr = r + (size_t)row * D;
            float acc = 0.f;
#pragma unroll 8
            for (int k = 0; k < D; k++)
                acc += rr[k] * w_rel[k * D + n];
            rout[(size_t)row * D + n] = acc;
        }
        return;
    }
    // x / r -> fp16; x_h also seeds g_A cols [512, 768)
    int gid = (b - GE_BLOCKS - MISC_BLOCKS) * 256 + threadIdx.x;
    if (gid < NN * 32) {
        int row = gid >> 5, c8 = gid & 31;
        const float4* src = (const float4*)(x + (size_t)row * D + c8 * 8);
        float4 v0 = src[0], v1 = src[1];
        float v[8] = {v0.x, v0.y, v0.z, v0.w, v1.x, v1.y, v1.z, v1.w};
        uint4 hv = pack_half8(v);
        *(uint4*)(g_xh + (size_t)row * D + c8 * 8) = hv;
        *(uint4*)(g_A + (size_t)row * KTOT + 512 + c8 * 8) = hv;
    } else {
        int g2 = gid - NN * 32;
        if (g2 < RR * 32) {
            int row = g2 >> 5, c8 = g2 & 31;
            const float4* src = (const float4*)(r + (size_t)row * D + c8 * 8);
            float4 v0 = src[0], v1 = src[1];
            float v[8] = {v0.x, v0.y, v0.z, v0.w, v1.x, v1.y, v1.z, v1.w};
            *(uint4*)(g_rh + (size_t)row * D + c8 * 8) = pack_half8(v);
        }
    }
}

// ---------------- launch 2: scan + dinv + start/cursor + edge fill (fused) ----------------
__global__ void k_scanfill(const int* __restrict__ rowp,
                           const int* __restrict__ colp,
                           const int* __restrict__ etp) {
    __shared__ int s[SCAN_BS];
    __shared__ int base_sh;
    int t = threadIdx.x;
    int bid = blockIdx.x;
    int i = bid * SCAN_BS + t;
    int v = (i < NN) ? g_zb.cnt[i] : 0;
    if (i < NN) g_dinv[i] = (v > 0) ? rsqrtf((float)v) : 0.f;
    s[t] = v;
    __syncthreads();
    for (int off = 1; off < SCAN_BS; off <<= 1) {
        int a = (t >= off) ? s[t - off] : 0;
        __syncthreads();
        s[t] += a;
        __syncthreads();
    }
    int incl = s[t];
    if (t == 0) {
        int btot = s[SCAN_BS - 1];
        while (atomicAdd(&g_zb.flag, 0) != bid) {}
        __threadfence();
        int b = g_zb.total;
        g_zb.total = b + btot;
        __threadfence();
        atomicExch(&g_zb.flag, bid + 1);
        base_sh = b;
    }
    __syncthreads();
    if (i < NN) {
        int st = base_sh + incl - v;
        g_start[i] = st;
        g_cursor[i] = st;
    }
    if (t == 0) {
        while (atomicAdd(&g_zb.flag, 0) != NB_SCAN) {}
        base_sh = 0;
    }
    __syncthreads();
    __threadfence();
    int nthreads = NB_SCAN * SCAN_BS;
    for (int e = bid * SCAN_BS + t; e < EE; e += nthreads) {
        int pos = atomicAdd(&g_cursor[rowp[e]], 1);
        unsigned pk = ((e < HALF_E) ? 0u : 0x80000000u) |
                      ((unsigned)etp[e] << 17) | (unsigned)colp[e];
        g_epack[pos] = pk;
    }
}

// ---------------- launch 3: aggregate, half2 regs + uniform branches ----------------
__global__ void k_aggregate() {
    int node = blockIdx.x * 8 + (threadIdx.x >> 5);
    if (node >= NN) return;
    int lane = threadIdx.x & 31;
    int base = lane * 8;
    size_t rb = (size_t)node * KTOT;

    __half2 zero = __float2half2_rn(0.f);
    __half2 ai0 = zero, ai1 = zero, ai2 = zero, ai3 = zero;
    __half2 ao0 = zero, ao1 = zero, ao2 = zero, ao3 = zero;

    int s = g_start[node];
    int c = g_zb.cnt[node];
    float di = g_dinv[node];
    int end = s + c;
    int p = s;

    for (; p + 2 <= end; p += 2) {
        unsigned pk0 = g_epack[p], pk1 = g_epack[p + 1];
        int cl0 = pk0 & 0x1FFFF, et0 = (pk0 >> 17) & 0x1FF;
        int cl1 = pk1 & 0x1FFFF, et1 = (pk1 >> 17) & 0x1FF;
        __half2 n0 = __float2half2_rn(di * g_dinv[cl0]);
        __half2 n1 = __float2half2_rn(di * g_dinv[cl1]);
        uint4 xa = *(const uint4*)(g_xh + (size_t)cl0 * D + base);
        uint4 ra = *(const uint4*)(g_rh + (size_t)et0 * D + base);
        uint4 xb = *(const uint4*)(g_xh + (size_t)cl1 * D + base);
        uint4 rv = *(const uint4*)(g_rh + (size_t)et1 * D + base);
        const __half2* xah = (const __half2*)&xa;
        const __half2* rah = (const __half2*)&ra;
        const __half2* xbh = (const __half2*)&xb;
        const __half2* rbh = (const __half2*)&rv;
        __half2 d00 = __hsub2(xah[0], rah[0]);
        __half2 d01 = __hsub2(xah[1], rah[1]);
        __half2 d02 = __hsub2(xah[2], rah[2]);
        __half2 d03 = __hsub2(xah[3], rah[3]);
        if (!(pk0 & 0x80000000u)) {
            ai0 = __hfma2(d00, n0, ai0);
            ai1 = __hfma2(d01, n0, ai1);
            ai2 = __hfma2(d02, n0, ai2);
            ai3 = __hfma2(d03, n0, ai3);
        } else {
            ao0 = __hfma2(d00, n0, ao0);
            ao1 = __hfma2(d01, n0, ao1);
            ao2 = __hfma2(d02, n0, ao2);
            ao3 = __hfma2(d03, n0, ao3);
        }
        __half2 d10 = __hsub2(xbh[0], rbh[0]);
        __half2 d11 = __hsub2(xbh[1], rbh[1]);
        __half2 d12 = __hsub2(xbh[2], rbh[2]);
        __half2 d13 = __hsub2(xbh[3], rbh[3]);
        if (!(pk1 & 0x80000000u)) {
            ai0 = __hfma2(d10, n1, ai0);
            ai1 = __hfma2(d11, n1, ai1);
            ai2 = __hfma2(d12, n1, ai2);
            ai3 = __hfma2(d13, n1, ai3);
        } else {
            ao0 = __hfma2(d10, n1, ao0);
            ao1 = __hfma2(d11, n1, ao1);
            ao2 = __hfma2(d12, n1, ao2);
            ao3 = __hfma2(d13, n1, ao3);
        }
    }
    if (p < end) {
        unsigned pk = g_epack[p];
        int cl = pk & 0x1FFFF, et = (pk >> 17) & 0x1FF;
        __half2 nrm = __float2half2_rn(di * g_dinv[cl]);
        uint4 xa = *(const uint4*)(g_xh + (size_t)cl * D + base);
        uint4 ra = *(const uint4*)(g_rh + (size_t)et * D + base);
        const __half2* xah = (const __half2*)&xa;
        const __half2* rah = (const __half2*)&ra;
        __half2 d00 = __hsub2(xah[0], rah[0]);
        __half2 d01 = __hsub2(xah[1], rah[1]);
        __half2 d02 = __hsub2(xah[2], rah[2]);
        __half2 d03 = __hsub2(xah[3], rah[3]);
        if (!(pk & 0x80000000u)) {
            ai0 = __hfma2(d00, nrm, ai0);
            ai1 = __hfma2(d01, nrm, ai1);
            ai2 = __hfma2(d02, nrm, ai2);
            ai3 = __hfma2(d03, nrm, ai3);
        } else {
            ao0 = __hfma2(d00, nrm, ao0);
            ao1 = __hfma2(d01, nrm, ao1);
            ao2 = __hfma2(d02, nrm, ao2);
            ao3 = __hfma2(d03, nrm, ao3);
        }
    }
    uint4 vin, vout;
    ((__half2*)&vin)[0] = ai0;  ((__half2*)&vin)[1] = ai1;
    ((__half2*)&vin)[2] = ai2;  ((__half2*)&vin)[3] = ai3;
    ((__half2*)&vout)[0] = ao0; ((__half2*)&vout)[1] = ao1;
    ((__half2*)&vout)[2] = ao2; ((__half2*)&vout)[3] = ao3;
    *(uint4*)(g_A + rb + base)       = vin;
    *(uint4*)(g_A + rb + 256 + base) = vout;
}

// ---------------- launch 4 (profiled): mma.sync fp16 GEMM, 4-stage ring, 1 sync/iter ----------------
__device__ __forceinline__ void load_stage(uint32_t sb, int buf, int kOff,
                                           int rowBase, int colBase, int tid) {
    uint32_t base = sb + buf * STAGE;
#pragma unroll
    for (int i = 0; i < 4; i++) {
        int c = tid + i * 256;
        int isB = c >> 9;
        int rem = c & 511;
        int row = rem >> 2, q = rem & 3;
        uint32_t dst = base + isB * ASPL + row * ROWB + q * 16;
        const __half* src;
        int sz = 16;
        if (!isB) {
            int gr = rowBase + row;
            if (gr >= NN) { gr = 0; sz = 0; }
            src = g_A + (size_t)gr * KTOT + kOff + q * 8;
        } else {
            int gc = colBase + row;
            src = g_B + (size_t)gc * KTOT + kOff + q * 8;
        }
        CP_ASYNC16(dst, (const void*)src, sz);
    }
}

__global__ void __launch_bounds__(256, 2)
k_gemm_mma(float* __restrict__ hout) {
    extern __shared__ char smem[];
    uint32_t sb = smem_u32(smem);
    int tid = threadIdx.x;
    int lane = tid & 31, wid = tid >> 5;
    int warp_m = wid & 1;
    int warp_n = wid >> 1;
    int colBase = blockIdx.x * 128;
    int rowBase = blockIdx.y * 128;

    float c[4][4][4];
#pragma unroll
    for (int i = 0; i < 4; i++)
#pragma unroll
        for (int j = 0; j < 4; j++)
#pragma unroll
            for (int q = 0; q < 4; q++) c[i][j][q] = 0.f;

#pragma unroll
    for (int s = 0; s < 3; s++) {
        load_stage(sb, s, s * 32, rowBase, colBase, tid);
        CP_COMMIT();
    }

    uint32_t a_off = (lane & 15) * ROWB + (lane >> 4) * 16;
    uint32_t b_off = (((lane >> 4) << 3) + (lane & 7)) * ROWB + ((lane >> 3) & 1) * 16;

    for (int it = 0; it < NKS; it++) {
        CP_WAIT2();
        __syncthreads();     // single barrier per iteration (4-stage ring)
        uint32_t st = sb + (it & 3) * STAGE;

#pragma unroll
        for (int ks2 = 0; ks2 < 2; ks2++) {
            uint32_t kb = ks2 * 32;
            uint32_t a[4][4];
#pragma unroll
            for (int mt = 0; mt < 4; mt++) {
                uint32_t addr = st + (warp_m * 64 + mt * 16) * ROWB + kb + a_off;
                LDMATRIX_X4(a[mt][0], a[mt][1], a[mt][2], a[mt][3], addr);
            }
            uint32_t b[2][4];
#pragma unroll
            for (int pr = 0; pr < 2; pr++) {
                uint32_t addr = st + ASPL + (warp_n * 32 + pr * 16) * ROWB + kb + b_off;
                LDMATRIX_X4(b[pr][0], b[pr][1], b[pr][2], b[pr][3], addr);
            }
#pragma unroll
            for (int mt = 0; mt < 4; mt++)
#pragma unroll
                for (int nt = 0; nt < 4; nt++) {
                    int pr = nt >> 1, ix = (nt & 1) * 2;
                    MMA16816F16(c[mt][nt], a[mt], b[pr][ix], b[pr][ix + 1]);
                }
        }
        if (it + 3 < NKS)
            load_stage(sb, (it + 3) & 3, (it + 3) * 32, rowBase, colBase, tid);
        CP_COMMIT();
    }

    // ---- epilogue: write hout (fp32) + per-CTA column stats ----
    float* cs  = (float*)(smem + SM_STATS);
    float* css = (float*)(smem + SM_STATS) + 128;
    __syncthreads();
    ((float*)(smem + SM_STATS))[tid] = 0.f;
    __syncthreads();

#pragma unroll
    for (int nt = 0; nt < 4; nt++) {
        int lcol = warp_n * 32 + nt * 8 + (lane & 3) * 2;
        int col = colBase + lcol;
        float b0 = g_bias2[col], b1 = g_bias2[col + 1];
        float s0 = 0.f, s1 = 0.f, q0 = 0.f, q1 = 0.f;
#pragma unroll
        for (int mt = 0; mt < 4; mt++) {
            int row = rowBase + warp_m * 64 + mt * 16 + (lane >> 2);
            if (row < NN) {
                float v0 = c[mt][nt][0] + b0, v1 = c[mt][nt][1] + b1;
                *(float2*)(hout + (size_t)row * D + col) = make_float2(v0, v1);
                s0 += v0; s1 += v1; q0 += v0 * v0; q1 += v1 * v1;
            }
            int row2 = row + 8;
            if (row2 < NN) {
                float v0 = c[mt][nt][2] + b0, v1 = c[mt][nt][3] + b1;
                *(float2*)(hout + (size_t)row2 * D + col) = make_float2(v0, v1);
                s0 += v0; s1 += v1; q0 += v0 * v0; q1 += v1 * v1;
            }
        }
        atomicAdd(&cs[lcol], s0);
        atomicAdd(&cs[lcol + 1], s1);
        atomicAdd(&css[lcol], q0);
        atomicAdd(&css[lcol + 1], q1);
    }
    __syncthreads();
    if (tid < 128) atomicAdd(&g_zb.colsum[colBase + tid], cs[tid]);
    else           atomicAdd(&g_zb.colsumsq[colBase + (tid - 128)], css[tid - 128]);
}

// ---------------- BN finalize / apply ----------------
__global__ void k_bn_finalize(const float* __restrict__ gamma,
                              const float* __restrict__ beta) {
    int c = threadIdx.x;
    float mean = g_zb.colsum[c] / (float)NN;
    float var = g_zb.colsumsq[c] / (float)NN - mean * mean;
    float inv = rsqrtf(var + BN_EPS);
    float sc = gamma[c] * inv;
    g_scale[c] = sc;
    g_shift[c] = beta[c] - mean * sc;
}
__global__ void k_bn_apply(float* __restrict__ hout) {
    size_t i4 = (size_t)blockIdx.x * blockDim.x + threadIdx.x;
    size_t total4 = (size_t)NN * D / 4;
    if (i4 < total4) {
        int c = (int)((i4 & 63) * 4);
        float4 v = *(float4*)(hout + i4 * 4);
        v.x = tanhf(v.x * g_scale[c + 0] + g_shift[c + 0]);
        v.y = tanhf(v.y * g_scale[c + 1] + g_shift[c + 1]);
        v.z = tanhf(v.z * g_scale[c + 2] + g_shift[c + 2]);
        v.w = tanhf(v.w * g_scale[c + 3] + g_shift[c + 3]);
        *(float4*)(hout + i4 * 4) = v;
    }
}

// ---------------- launch ----------------
extern "C" void kernel_launch(void* const* d_in, const int* in_sizes, int n_in,
                              void* d_out, int out_size) {
    const float* x        = (const float*)d_in[0];
    const float* r        = (const float*)d_in[1];
    const float* w_in     = (const float*)d_in[2];
    const float* w_out    = (const float*)d_in[3];
    const float* w_loop   = (const float*)d_in[4];
    const float* w_rel    = (const float*)d_in[5];
    const float* loop_rel = (const float*)d_in[6];
    const float* bias     = (const float*)d_in[7];
    const float* bn_gamma = (const float*)d_in[8];
    const float* bn_beta  = (const float*)d_in[9];
    const int*   edge_idx = (const int*)d_in[10];
    const int*   edge_typ = (const int*)d_in[11];

    const int* rowp = edge_idx;
    const int* colp = edge_idx + EE;

    float* hout = (float*)d_out;
    float* rout = (float*)d_out + (size_t)NN * D;

    cudaFuncSetAttribute(k_gemm_mma, cudaFuncAttributeMaxDynamicSharedMemorySize, SMEM_GEMM);

    void* zb_addr = nullptr;
    cudaGetSymbolAddress(&zb_addr, g_zb);
    cudaMemsetAsync(zb_addr, 0, sizeof(ZeroBlk));

    k_countmisc<<<GE_BLOCKS + MISC_BLOCKS + XCONV_BLOCKS, 256>>>(
        rowp, x, w_in, w_out, w_loop, bias, loop_rel, r, w_rel, rout);      // 1
    k_scanfill<<<NB_SCAN, SCAN_BS>>>(rowp, colp, edge_typ);                 // 2
    k_aggregate<<<(NN + 7) / 8, 256>>>();                                   // 3
    dim3 gg(2, GEMM_MBLK);
    k_gemm_mma<<<gg, 256, SMEM_GEMM>>>(hout);                               // 4 (profiled)
    k_bn_finalize<<<1, D>>>(bn_gamma, bn_beta);                             // 5
    k_bn_apply<<<(int)(((size_t)NN * D / 4 + 255) / 256), 256>>>(hout);     // 6
}